// round 4
// baseline (speedup 1.0000x reference)
#include <cuda_runtime.h>

#define BB 4
#define LL 1024
#define DD 768
#define HH 12
#define DHH 64

// Scratch (static device globals — allocation-free per harness rules)
__device__ float g_M[(size_t)HH * DD * DD];          // q_n^T k_n
__device__ float g_A[(size_t)BB * HH * LL * DD];     // X_b M_n
__device__ float g_S[(size_t)BB * HH * LL * LL];     // scores / softmax
__device__ float g_V[(size_t)BB * HH * LL * DHH];    // X_b v_n^T
// tf32-prerounded copies of the inputs (cp.async copies raw bytes, so
// rounding must happen before the GEMM reads them)
__device__ float g_x[(size_t)BB * LL * DD];
__device__ float g_k[(size_t)HH * DD * DD];
__device__ float g_q[(size_t)HH * DD * DD];
__device__ float g_v[(size_t)HH * DHH * DD];

__device__ __forceinline__ unsigned f2tf(float x) {
    unsigned u;
    asm("cvt.rna.tf32.f32 %0, %1;" : "=r"(u) : "f"(x));
    return u;
}
__device__ __forceinline__ float rtf(float x) { return __uint_as_float(f2tf(x)); }

__device__ __forceinline__ void mma_tf32(float* c, const unsigned* a, const unsigned* b) {
    asm volatile(
        "mma.sync.aligned.m16n8k8.row.col.f32.tf32.tf32.f32 "
        "{%0,%1,%2,%3}, {%4,%5,%6,%7}, {%8,%9}, {%0,%1,%2,%3};"
        : "+f"(c[0]), "+f"(c[1]), "+f"(c[2]), "+f"(c[3])
        : "r"(a[0]), "r"(a[1]), "r"(a[2]), "r"(a[3]), "r"(b[0]), "r"(b[1]));
}

#define SWC(row) ((((row) >> 2) & 7) << 2)

__device__ __forceinline__ unsigned sa(const void* p) {
    return (unsigned)__cvta_generic_to_shared(p);
}
__device__ __forceinline__ void cpa16(unsigned saddr, const void* g, bool pred) {
    int sz = pred ? 16 : 0;
    asm volatile("cp.async.cg.shared.global [%0], [%1], 16, %2;\n"
                 :: "r"(saddr), "l"(g), "r"(sz));
}
__device__ __forceinline__ void cp_commit() {
    asm volatile("cp.async.commit_group;\n" ::: "memory");
}
__device__ __forceinline__ void cp_wait1() {
    asm volatile("cp.async.wait_group 1;\n" ::: "memory");
}

// ---------------------------------------------------------------------------
// Batched tf32 tensor-core GEMM, cp.async double-buffered.
//  C[m,n] = sum_k opA(A)[m,k] * opB(B)[k,n]
//  !TA: A[m*lda+k]   TA: A[k*lda+m]   !TB: B[k*ldb+n]   TB: B[n*ldb+k]
// Block 128x128x16(x2 stages), 8 warps (2M x 4N) of 64x32.
// M, K multiples of 128/16 (true at all call sites); N may be < BN (guarded).
// RND: round output to tf32 (for intermediates consumed by later GEMMs).
// smem layouts:
//   KM (k-major gmem rows feed it naturally when MN dim is contiguous):
//       tile[k][x ^ SWC(k)], row stride 136 — used for TA(A) / !TB(B)
//   XM (k contiguous in gmem): tile[x][k], row stride 20 — used for !TA / TB
// ---------------------------------------------------------------------------
template<bool TA, bool TB, bool RND>
__global__ __launch_bounds__(256)
void gemm_tc(const float* __restrict__ Ag, const float* __restrict__ Bg,
             float* __restrict__ Cg, int M, int N, int K,
             int lda, int ldb, int ldc,
             long as1, long as2, long bs1, long bs2, long cs1, long cs2)
{
    __shared__ __align__(16) float As[2][2560];
    __shared__ __align__(16) float Bs[2][2560];

    const int z = blockIdx.z;
    const float* A = Ag + (long)(z / HH) * as1 + (long)(z % HH) * as2;
    const float* B = Bg + (long)(z / HH) * bs1 + (long)(z % HH) * bs2;
    float* C = Cg + (long)(z / HH) * cs1 + (long)(z % HH) * cs2;

    const int m0 = blockIdx.y * 128;
    const int n0 = blockIdx.x * 128;
    const int tid = threadIdx.x;
    const int lane = tid & 31;
    const int wid = tid >> 5;              // 0..7
    const int wm = (wid & 1) * 64;         // 2 warps in M
    const int wn = (wid >> 1) * 32;        // 4 warps in N
    const int lm = lane >> 2;              // 0..7
    const int lk = lane & 3;               // 0..3

    float acc[4][4][4];
    #pragma unroll
    for (int i = 0; i < 4; i++)
        #pragma unroll
        for (int j = 0; j < 4; j++)
            #pragma unroll
            for (int r = 0; r < 4; r++) acc[i][j][r] = 0.f;

    // ---- stage loaders: 512 16B-chunks per operand tile, 2 per thread ----
    auto load_stage = [&](int buf, int kt) {
        #pragma unroll
        for (int i = 0; i < 2; i++) {
            const int c4 = tid + i * 256;
            // A tile
            if (!TA) {                       // XM: [m][k] stride 20
                const int m = c4 >> 2, kq = (c4 & 3) << 2;
                cpa16(sa(&As[buf][m * 20 + kq]),
                      &A[(long)(m0 + m) * lda + kt + kq], true);
            } else {                         // KM: [k][m^swz]
                const int k = c4 >> 5, m4 = (c4 & 31) << 2;
                cpa16(sa(&As[buf][k * 136 + (m4 ^ SWC(k))]),
                      &A[(long)(kt + k) * lda + m0 + m4], true);
            }
            // B tile
            if (TB) {                        // XM: [n][k] stride 20
                const int n = c4 >> 2, kq = (c4 & 3) << 2;
                const bool p = (n0 + n) < N;
                cpa16(sa(&Bs[buf][n * 20 + kq]),
                      &B[(long)(p ? n0 + n : 0) * ldb + kt + kq], p);
            } else {                         // KM: [k][n^swz]
                const int k = c4 >> 5, n4 = (c4 & 31) << 2;
                const bool p = (n0 + n4) < N;
                cpa16(sa(&Bs[buf][k * 136 + (n4 ^ SWC(k))]),
                      &B[(long)(kt + k) * ldb + (p ? n0 + n4 : 0)], p);
            }
        }
    };

    auto compute = [&](int buf) {
        const float* __restrict__ Ab = As[buf];
        const float* __restrict__ Bb = Bs[buf];
        #pragma unroll
        for (int ks = 0; ks < 2; ks++) {
            const int r1 = ks * 8 + lk;
            const int r2 = r1 + 4;
            unsigned a[4][4], b[4][2];
            if (!TA) {
                #pragma unroll
                for (int mt = 0; mt < 4; mt++) {
                    const int mr = wm + mt * 16 + lm;
                    a[mt][0] = __float_as_uint(Ab[mr * 20 + r1]);
                    a[mt][1] = __float_as_uint(Ab[(mr + 8) * 20 + r1]);
                    a[mt][2] = __float_as_uint(Ab[mr * 20 + r2]);
                    a[mt][3] = __float_as_uint(Ab[(mr + 8) * 20 + r2]);
                }
            } else {
                const int c1 = SWC(r1), c2 = SWC(r2);
                #pragma unroll
                for (int mt = 0; mt < 4; mt++) {
                    const int mr = wm + mt * 16 + lm;
                    a[mt][0] = __float_as_uint(Ab[r1 * 136 + (mr ^ c1)]);
                    a[mt][1] = __float_as_uint(Ab[r1 * 136 + ((mr + 8) ^ c1)]);
                    a[mt][2] = __float_as_uint(Ab[r2 * 136 + (mr ^ c2)]);
                    a[mt][3] = __float_as_uint(Ab[r2 * 136 + ((mr + 8) ^ c2)]);
                }
            }
            if (!TB) {
                const int c1 = SWC(r1), c2 = SWC(r2);
                #pragma unroll
                for (int nt = 0; nt < 4; nt++) {
                    const int nc = wn + nt * 8 + lm;
                    b[nt][0] = __float_as_uint(Bb[r1 * 136 + (nc ^ c1)]);
                    b[nt][1] = __float_as_uint(Bb[r2 * 136 + (nc ^ c2)]);
                }
            } else {
                #pragma unroll
                for (int nt = 0; nt < 4; nt++) {
                    const int nc = wn + nt * 8 + lm;
                    b[nt][0] = __float_as_uint(Bb[nc * 20 + r1]);
                    b[nt][1] = __float_as_uint(Bb[nc * 20 + r2]);
                }
            }
            #pragma unroll
            for (int mt = 0; mt < 4; mt++)
                #pragma unroll
                for (int nt = 0; nt < 4; nt++)
                    mma_tf32(acc[mt][nt], a[mt], b[nt]);
        }
    };

    // ---- 2-stage pipeline ----
    const int nk = K / 16;
    load_stage(0, 0);
    cp_commit();
    load_stage(1, 16);
    cp_commit();
    for (int t = 0; t < nk; t++) {
        cp_wait1();
        __syncthreads();
        compute(t & 1);
        __syncthreads();
        const int kt = (t + 2) * 16;
        if (kt < K) load_stage(t & 1, kt);
        cp_commit();
    }

    // ---- epilogue ----
    #pragma unroll
    for (int mt = 0; mt < 4; mt++) {
        const int r0 = m0 + wm + mt * 16 + lm;
        #pragma unroll
        for (int nt = 0; nt < 4; nt++) {
            const int c0 = n0 + wn + nt * 8 + 2 * lk;
            if (c0 < N) {
                float v0 = acc[mt][nt][0], v1 = acc[mt][nt][1];
                float v2 = acc[mt][nt][2], v3 = acc[mt][nt][3];
                if (RND) { v0 = rtf(v0); v1 = rtf(v1); v2 = rtf(v2); v3 = rtf(v3); }
                C[(long)r0 * ldc + c0]           = v0;
                C[(long)r0 * ldc + c0 + 1]       = v1;
                C[(long)(r0 + 8) * ldc + c0]     = v2;
                C[(long)(r0 + 8) * ldc + c0 + 1] = v3;
            }
        }
    }
}

// ---------------------------------------------------------------------------
// Elementwise tf32 pre-rounding (float4 granularity; n4 = n/4)
// ---------------------------------------------------------------------------
__global__ void round_kernel(const float* __restrict__ in, float* __restrict__ out, int n4)
{
    const int i = blockIdx.x * 256 + threadIdx.x;
    if (i < n4) {
        float4 v = ((const float4*)in)[i];
        v.x = rtf(v.x); v.y = rtf(v.y); v.z = rtf(v.z); v.w = rtf(v.w);
        ((float4*)out)[i] = v;
    }
}

// ---------------------------------------------------------------------------
// Row softmax (in place), output rounded to tf32 (it feeds GEMM 6).
// ---------------------------------------------------------------------------
__global__ void softmax_kernel(float* __restrict__ S, int cols)
{
    float* p = S + (long)blockIdx.x * cols;
    const int tid = threadIdx.x;
    __shared__ float red[8];

    float vmax = -1e30f;
    for (int i = tid; i < cols; i += 256) vmax = fmaxf(vmax, p[i]);
    #pragma unroll
    for (int o = 16; o > 0; o >>= 1) vmax = fmaxf(vmax, __shfl_xor_sync(~0u, vmax, o));
    if ((tid & 31) == 0) red[tid >> 5] = vmax;
    __syncthreads();
    if (tid < 32) {
        float v = (tid < 8) ? red[tid] : -1e30f;
        #pragma unroll
        for (int o = 4; o > 0; o >>= 1) v = fmaxf(v, __shfl_xor_sync(~0u, v, o));
        if (tid == 0) red[0] = v;
    }
    __syncthreads();
    vmax = red[0];
    __syncthreads();

    float s = 0.f;
    for (int i = tid; i < cols; i += 256) {
        const float e = __expf(p[i] - vmax);
        p[i] = e;
        s += e;
    }
    #pragma unroll
    for (int o = 16; o > 0; o >>= 1) s += __shfl_xor_sync(~0u, s, o);
    if ((tid & 31) == 0) red[tid >> 5] = s;
    __syncthreads();
    if (tid < 32) {
        float v = (tid < 8) ? red[tid] : 0.f;
        #pragma unroll
        for (int o = 4; o > 0; o >>= 1) v += __shfl_xor_sync(~0u, v, o);
        if (tid == 0) red[0] = v;
    }
    __syncthreads();
    const float inv = 1.0f / red[0];
    for (int i = tid; i < cols; i += 256) p[i] = rtf(p[i] * inv);
}

// ---------------------------------------------------------------------------
extern "C" void kernel_launch(void* const* d_in, const int* in_sizes, int n_in,
                              void* d_out, int out_size)
{
    const float* x = (const float*)d_in[0];   // [B, L, D]
    const float* k = (const float*)d_in[1];   // [H, D, D]
    const float* q = (const float*)d_in[2];   // [H, D, D]
    const float* v = (const float*)d_in[3];   // [H, DH, D]
    float* out = (float*)d_out;               // [B, L, D]

    float *pM, *pA, *pS, *pV, *px, *pk, *pq, *pv;
    cudaGetSymbolAddress((void**)&pM, g_M);
    cudaGetSymbolAddress((void**)&pA, g_A);
    cudaGetSymbolAddress((void**)&pS, g_S);
    cudaGetSymbolAddress((void**)&pV, g_V);
    cudaGetSymbolAddress((void**)&px, g_x);
    cudaGetSymbolAddress((void**)&pk, g_k);
    cudaGetSymbolAddress((void**)&pq, g_q);
    cudaGetSymbolAddress((void**)&pv, g_v);

    const long LD  = (long)LL * DD;
    const long L2  = (long)LL * LL;
    const long DSQ = (long)DD * DD;
    const long LDH = (long)LL * DHH;

    // 0) pre-round inputs to tf32
    {
        const int nx = BB * LL * DD / 4, nk2 = HH * DD * DD / 4, nv = HH * DHH * DD / 4;
        round_kernel<<<(nx + 255) / 256, 256>>>(x, px, nx);
        round_kernel<<<(nk2 + 255) / 256, 256>>>(k, pk, nk2);
        round_kernel<<<(nk2 + 255) / 256, 256>>>(q, pq, nk2);
        round_kernel<<<(nv + 255) / 256, 256>>>(v, pv, nv);
    }

    dim3 blk(256);

    // 1) M_n = q_n^T * k_n : [D,D,D], batch 12          (TA, !TB)  -> round
    gemm_tc<true, false, true><<<dim3(DD/128, DD/128, HH), blk>>>(
        pq, pk, pM, DD, DD, DD, DD, DD, DD,
        0, DSQ,   0, DSQ,   0, DSQ);

    // 2) A_bn = X_b * M_n : [L,D]x[D,D], batch 48       (!TA,!TB)  -> round
    gemm_tc<false, false, true><<<dim3(DD/128, LL/128, BB*HH), blk>>>(
        px, pM, pA, LL, DD, DD, DD, DD, DD,
        LD, 0,    0, DSQ,   HH*LD, LD);

    // 3) S = A_bn * X_b^T : [L,D]x[D,L], batch 48       (!TA, TB)  (softmax rounds)
    gemm_tc<false, true, false><<<dim3(LL/128, LL/128, BB*HH), blk>>>(
        pA, px, pS, LL, LL, DD, DD, DD, LL,
        HH*LD, LD,   LD, 0,   HH*L2, L2);

    // 4) softmax over last dim of S (rounds output to tf32)
    softmax_kernel<<<dim3(BB*HH*LL), dim3(256)>>>(pS, LL);

    // 5) Vt = X_b * v_n^T : [L,D]x[D,DH], batch 48      (!TA, TB)  -> round
    gemm_tc<false, true, true><<<dim3(1, LL/128, BB*HH), blk>>>(
        px, pv, pV, LL, DHH, DD, DD, DD, DHH,
        LD, 0,    0, (long)DHH*DD,   HH*LDH, LDH);

    // 6) out = S * Vt : [L,L]x[L,DH], batch 48          (!TA,!TB)  final, no round
    gemm_tc<false, false, false><<<dim3(1, LL/128, BB*HH), blk>>>(
        pS, pV, out, LL, DHH, LL, LL, DHH, DD,
        HH*L2, L2,   HH*LDH, LDH,   LD, DHH);
}

// round 5
// speedup vs baseline: 1.2160x; 1.2160x over previous
#include <cuda_runtime.h>
#include <cstdint>

#define BB 4
#define LL 1024
#define DD 768
#define HH 12
#define DHH 64

// Packed scratch: every GEMM operand stored as contiguous tiles in the exact
// smem layout the GEMM consumes.
//   XM tile (k-contiguous operand): 128 rows x 20 floats (16 data + 4 pad) = 10240B
//   KM tile (mn-contiguous operand): 16 k x 136 floats (128 data ^swz + 8 pad) = 8704B
__device__ __align__(1024) float g_xp [(size_t)BB * 8 * 48 * 2560];      // x   XM
__device__ __align__(1024) float g_qp [(size_t)HH * 6 * 48 * 2176];      // q^T KM
__device__ __align__(1024) float g_kp [(size_t)HH * 6 * 48 * 2176];      // k^T KM
__device__ __align__(1024) float g_vp [(size_t)HH * 48 * 2560];          // v   XM (rows 64..127 zero)
__device__ __align__(1024) float g_Mp [(size_t)HH * 6 * 48 * 2176];      // M   KM
__device__ __align__(1024) float g_Ap [(size_t)BB * HH * 8 * 48 * 2560]; // A   XM
__device__ __align__(1024) float g_Sp [(size_t)BB * HH * 8 * 64 * 2560]; // S   XM
__device__ __align__(1024) float g_Vtp[(size_t)BB * HH * 64 * 2176];     // Vt  KM

__device__ __forceinline__ unsigned f2tf(float x) {
    unsigned u; asm("cvt.rna.tf32.f32 %0, %1;" : "=r"(u) : "f"(x)); return u;
}
__device__ __forceinline__ float rtf(float x) { return __uint_as_float(f2tf(x)); }

__device__ __forceinline__ void mma_tf32(float* c, const unsigned* a, const unsigned* b) {
    asm volatile(
        "mma.sync.aligned.m16n8k8.row.col.f32.tf32.tf32.f32 "
        "{%0,%1,%2,%3}, {%4,%5,%6,%7}, {%8,%9}, {%0,%1,%2,%3};"
        : "+f"(c[0]), "+f"(c[1]), "+f"(c[2]), "+f"(c[3])
        : "r"(a[0]), "r"(a[1]), "r"(a[2]), "r"(a[3]), "r"(b[0]), "r"(b[1]));
}

#define SWC(row) ((((row) >> 2) & 7) << 2)

__device__ __forceinline__ uint32_t sa32(const void* p) {
    return (uint32_t)__cvta_generic_to_shared(p);
}
__device__ __forceinline__ void bulk_g2s(uint32_t dst, const float* src,
                                         uint32_t bytes, uint32_t mbar) {
    asm volatile(
        "cp.async.bulk.shared::cluster.global.mbarrier::complete_tx::bytes [%0], [%1], %2, [%3];"
        :: "r"(dst), "l"(src), "r"(bytes), "r"(mbar) : "memory");
}
__device__ __forceinline__ void bar_wait(uint32_t mbar, unsigned parity) {
    asm volatile(
        "{\n\t.reg .pred P;\n\t"
        "W_%=:\n\t"
        "mbarrier.try_wait.parity.acquire.cta.shared::cta.b64 P, [%0], %1, 0x989680;\n\t"
        "@P bra D_%=;\n\t"
        "bra W_%=;\n\t"
        "D_%=:\n\t}"
        :: "r"(mbar), "r"(parity) : "memory");
}

// ---------------------------------------------------------------------------
// Bulk-fed tf32 tensor GEMM on packed tiles. Block 128x128x16, 2-stage ring.
// AZ/BZ: z-index mapping 0:z 1:z/HH 2:z%HH.  TA/TB: operand layout (KM if
// "transposed", XM otherwise) — compute() identical to round-3 kernel.
// EPI: 0 plain row-major, 1 XM-packed, 2 KM-packed. RND: tf32-round output.
// ---------------------------------------------------------------------------
template<int AZ, int BZ, bool TA, bool TB, int EPI, bool RND>
__global__ __launch_bounds__(256)
void gemm_bulk(const float* __restrict__ Apk, const float* __restrict__ Bpk,
               float* __restrict__ Cg, int nkst, int N, int cNK, long czs,
               long cs1, long cs2, int ldc)
{
    __shared__ __align__(16) float As[2][2560];
    __shared__ __align__(16) float Bs[2][2560];
    __shared__ __align__(8) uint64_t mb[2];

    const int z = blockIdx.z;
    const long zA = (AZ == 1) ? z / HH : z;
    const long zB = (BZ == 1) ? z / HH : (BZ == 2 ? z % HH : z);
    constexpr int ABLOB = TA ? 2176 : 2560;
    constexpr int BBLOB = TB ? 2560 : 2176;
    constexpr uint32_t ABYT = ABLOB * 4, BBYT = BBLOB * 4;

    const float* Abase = Apk + ((zA * gridDim.y + blockIdx.y) * (long)nkst) * ABLOB;
    const float* Bbase = Bpk + ((zB * gridDim.x + blockIdx.x) * (long)nkst) * BBLOB;

    const int tid = threadIdx.x;
    const int lane = tid & 31;
    const int wid = tid >> 5;
    const int wm = (wid & 1) * 64;
    const int wn = (wid >> 1) * 32;
    const int lm = lane >> 2;
    const int lk = lane & 3;
    const int m0 = blockIdx.y * 128;
    const int n0 = blockIdx.x * 128;

    float acc[4][4][4];
    #pragma unroll
    for (int i = 0; i < 4; i++)
        #pragma unroll
        for (int j = 0; j < 4; j++)
            #pragma unroll
            for (int r = 0; r < 4; r++) acc[i][j][r] = 0.f;

    if (tid == 0) {
        asm volatile("mbarrier.init.shared.b64 [%0], 1;" :: "r"(sa32(&mb[0])) : "memory");
        asm volatile("mbarrier.init.shared.b64 [%0], 1;" :: "r"(sa32(&mb[1])) : "memory");
    }
    __syncthreads();

    auto issue = [&](int buf, int kst) {
        const uint32_t m = sa32(&mb[buf]);
        asm volatile("mbarrier.arrive.expect_tx.shared.b64 _, [%0], %1;"
                     :: "r"(m), "r"(ABYT + BBYT) : "memory");
        bulk_g2s(sa32(&As[buf][0]), Abase + (long)kst * ABLOB, ABYT, m);
        bulk_g2s(sa32(&Bs[buf][0]), Bbase + (long)kst * BBLOB, BBYT, m);
    };
    if (tid == 0) { issue(0, 0); issue(1, 1); }

    auto compute = [&](int buf) {
        const float* __restrict__ Ab = As[buf];
        const float* __restrict__ Bb = Bs[buf];
        #pragma unroll
        for (int ks = 0; ks < 2; ks++) {
            const int r1 = ks * 8 + lk, r2 = r1 + 4;
            unsigned a[4][4], b[4][2];
            if (!TA) {
                #pragma unroll
                for (int mt = 0; mt < 4; mt++) {
                    const int mr = wm + mt * 16 + lm;
                    a[mt][0] = __float_as_uint(Ab[mr * 20 + r1]);
                    a[mt][1] = __float_as_uint(Ab[(mr + 8) * 20 + r1]);
                    a[mt][2] = __float_as_uint(Ab[mr * 20 + r2]);
                    a[mt][3] = __float_as_uint(Ab[(mr + 8) * 20 + r2]);
                }
            } else {
                const int c1 = SWC(r1), c2 = SWC(r2);
                #pragma unroll
                for (int mt = 0; mt < 4; mt++) {
                    const int mr = wm + mt * 16 + lm;
                    a[mt][0] = __float_as_uint(Ab[r1 * 136 + (mr ^ c1)]);
                    a[mt][1] = __float_as_uint(Ab[r1 * 136 + ((mr + 8) ^ c1)]);
                    a[mt][2] = __float_as_uint(Ab[r2 * 136 + (mr ^ c2)]);
                    a[mt][3] = __float_as_uint(Ab[r2 * 136 + ((mr + 8) ^ c2)]);
                }
            }
            if (!TB) {
                const int c1 = SWC(r1), c2 = SWC(r2);
                #pragma unroll
                for (int nt = 0; nt < 4; nt++) {
                    const int nc = wn + nt * 8 + lm;
                    b[nt][0] = __float_as_uint(Bb[r1 * 136 + (nc ^ c1)]);
                    b[nt][1] = __float_as_uint(Bb[r2 * 136 + (nc ^ c2)]);
                }
            } else {
                #pragma unroll
                for (int nt = 0; nt < 4; nt++) {
                    const int nc = wn + nt * 8 + lm;
                    b[nt][0] = __float_as_uint(Bb[nc * 20 + r1]);
                    b[nt][1] = __float_as_uint(Bb[nc * 20 + r2]);
                }
            }
            #pragma unroll
            for (int mt = 0; mt < 4; mt++)
                #pragma unroll
                for (int nt = 0; nt < 4; nt++)
                    mma_tf32(acc[mt][nt], a[mt], b[nt]);
        }
    };

    unsigned ph[2] = {0, 0};
    for (int t = 0; t < nkst; t++) {
        const int buf = t & 1;
        bar_wait(sa32(&mb[buf]), ph[buf]);
        ph[buf] ^= 1;
        compute(buf);
        __syncthreads();
        if (t + 2 < nkst && tid == 0) issue(buf, t + 2);
    }

    // ---- epilogue ----
    #pragma unroll
    for (int mt = 0; mt < 4; mt++) {
        const int r0 = m0 + wm + mt * 16 + lm;
        #pragma unroll
        for (int nt = 0; nt < 4; nt++) {
            const int c0 = n0 + wn + nt * 8 + 2 * lk;
            if (c0 >= N) continue;
            float v0 = acc[mt][nt][0], v1 = acc[mt][nt][1];
            float v2 = acc[mt][nt][2], v3 = acc[mt][nt][3];
            if (RND) { v0 = rtf(v0); v1 = rtf(v1); v2 = rtf(v2); v3 = rtf(v3); }
            if (EPI == 0) {
                float* C = Cg + (long)(z / HH) * cs1 + (long)(z % HH) * cs2;
                *(float2*)&C[(long)r0 * ldc + c0]       = make_float2(v0, v1);
                *(float2*)&C[(long)(r0 + 8) * ldc + c0] = make_float2(v2, v3);
            } else if (EPI == 1) {
                float* p = Cg + (long)z * czs
                         + (((long)(r0 >> 7) * cNK) + (c0 >> 4)) * 2560
                         + (r0 & 127) * 20 + (c0 & 15);
                *(float2*)p         = make_float2(v0, v1);
                *(float2*)(p + 160) = make_float2(v2, v3);
            } else {
                float* p = Cg + (long)z * czs
                         + (((long)(c0 >> 7) * cNK) + (r0 >> 4)) * 2176;
                const int rr = r0 & 15, rr2 = rr + 8, cc = c0 & 127;
                *(float2*)&p[rr * 136 + (cc ^ SWC(rr))]   = make_float2(v0, v1);
                *(float2*)&p[rr2 * 136 + (cc ^ SWC(rr2))] = make_float2(v2, v3);
            }
        }
    }
}

// ---------------------------------------------------------------------------
// Pack kernels (tf32-round inputs into packed tile layouts)
// ---------------------------------------------------------------------------
__global__ void pack_x(const float* __restrict__ x, float* __restrict__ xp) {
    // grid (48, 8, 4): (kst, mtile, b) -> XM blob
    float* blob = xp + (((long)blockIdx.z * 8 + blockIdx.y) * 48 + blockIdx.x) * 2560;
    const float* src = x + ((long)blockIdx.z * LL + blockIdx.y * 128) * DD + blockIdx.x * 16;
    #pragma unroll
    for (int i = 0; i < 2; i++) {
        const int t = threadIdx.x + i * 256;
        const int row = t >> 2, kq = (t & 3) << 2;
        float4 v = *(const float4*)&src[(long)row * DD + kq];
        v.x = rtf(v.x); v.y = rtf(v.y); v.z = rtf(v.z); v.w = rtf(v.w);
        *(float4*)&blob[row * 20 + kq] = v;
    }
}
__global__ void pack_qk(const float* __restrict__ in, float* __restrict__ op) {
    // grid (48, 6, 12): (kst, xtile, h) -> KM blob (transposed consume)
    float* blob = op + (((long)blockIdx.z * 6 + blockIdx.y) * 48 + blockIdx.x) * 2176;
    const float* src = in + ((long)blockIdx.z * DD + blockIdx.x * 16) * DD + blockIdx.y * 128;
    #pragma unroll
    for (int i = 0; i < 2; i++) {
        const int t = threadIdx.x + i * 256;
        const int c = t >> 5, x4 = (t & 31) << 2;
        float4 v = *(const float4*)&src[(long)c * DD + x4];
        v.x = rtf(v.x); v.y = rtf(v.y); v.z = rtf(v.z); v.w = rtf(v.w);
        *(float4*)&blob[c * 136 + (x4 ^ SWC(c))] = v;
    }
}
__global__ void pack_v(const float* __restrict__ v, float* __restrict__ vp) {
    // grid (48, 1, 12): XM blob, rows 64..127 zeroed
    float* blob = vp + ((long)blockIdx.z * 48 + blockIdx.x) * 2560;
    const float* src = v + (long)blockIdx.z * DHH * DD + blockIdx.x * 16;
    #pragma unroll
    for (int i = 0; i < 2; i++) {
        const int t = threadIdx.x + i * 256;
        const int row = t >> 2, kq = (t & 3) << 2;
        float4 w = make_float4(0.f, 0.f, 0.f, 0.f);
        if (row < DHH) {
            w = *(const float4*)&src[(long)row * DD + kq];
            w.x = rtf(w.x); w.y = rtf(w.y); w.z = rtf(w.z); w.w = rtf(w.w);
        }
        *(float4*)&blob[row * 20 + kq] = w;
    }
}

// ---------------------------------------------------------------------------
// Row softmax on XM-packed S (in place), output tf32-rounded.
// ---------------------------------------------------------------------------
__global__ void softmax_p(float* __restrict__ Sp) {
    const int z = blockIdx.x >> 10;
    const int l = blockIdx.x & 1023;
    float* base = Sp + ((long)(z * 8 + (l >> 7)) * 64) * 2560 + (l & 127) * 20;
    const int tid = threadIdx.x;
    __shared__ float red[8];

    float vmax = -1e30f;
    #pragma unroll
    for (int j = 0; j < 4; j++) {
        const int c = tid + j * 256;
        vmax = fmaxf(vmax, base[(c >> 4) * 2560 + (c & 15)]);
    }
    #pragma unroll
    for (int o = 16; o > 0; o >>= 1) vmax = fmaxf(vmax, __shfl_xor_sync(~0u, vmax, o));
    if ((tid & 31) == 0) red[tid >> 5] = vmax;
    __syncthreads();
    if (tid < 32) {
        float w = (tid < 8) ? red[tid] : -1e30f;
        #pragma unroll
        for (int o = 4; o > 0; o >>= 1) w = fmaxf(w, __shfl_xor_sync(~0u, w, o));
        if (tid == 0) red[0] = w;
    }
    __syncthreads();
    vmax = red[0];
    __syncthreads();

    float s = 0.f;
    float ev[4];
    #pragma unroll
    for (int j = 0; j < 4; j++) {
        const int c = tid + j * 256;
        ev[j] = __expf(base[(c >> 4) * 2560 + (c & 15)] - vmax);
        s += ev[j];
    }
    #pragma unroll
    for (int o = 16; o > 0; o >>= 1) s += __shfl_xor_sync(~0u, s, o);
    if ((tid & 31) == 0) red[tid >> 5] = s;
    __syncthreads();
    if (tid < 32) {
        float w = (tid < 8) ? red[tid] : 0.f;
        #pragma unroll
        for (int o = 4; o > 0; o >>= 1) w += __shfl_xor_sync(~0u, w, o);
        if (tid == 0) red[0] = w;
    }
    __syncthreads();
    const float inv = 1.0f / red[0];
    #pragma unroll
    for (int j = 0; j < 4; j++) {
        const int c = tid + j * 256;
        base[(c >> 4) * 2560 + (c & 15)] = rtf(ev[j] * inv);
    }
}

// ---------------------------------------------------------------------------
extern "C" void kernel_launch(void* const* d_in, const int* in_sizes, int n_in,
                              void* d_out, int out_size)
{
    const float* x = (const float*)d_in[0];
    const float* k = (const float*)d_in[1];
    const float* q = (const float*)d_in[2];
    const float* v = (const float*)d_in[3];
    float* out = (float*)d_out;

    float *xp, *qp, *kp, *vp, *Mp, *Ap, *Sp, *Vtp;
    cudaGetSymbolAddress((void**)&xp, g_xp);
    cudaGetSymbolAddress((void**)&qp, g_qp);
    cudaGetSymbolAddress((void**)&kp, g_kp);
    cudaGetSymbolAddress((void**)&vp, g_vp);
    cudaGetSymbolAddress((void**)&Mp, g_Mp);
    cudaGetSymbolAddress((void**)&Ap, g_Ap);
    cudaGetSymbolAddress((void**)&Sp, g_Sp);
    cudaGetSymbolAddress((void**)&Vtp, g_Vtp);

    // 0) pack inputs (tf32-rounded) into tile layouts
    pack_x <<<dim3(48, 8, BB), 256>>>(x, xp);
    pack_qk<<<dim3(48, 6, HH), 256>>>(q, qp);
    pack_qk<<<dim3(48, 6, HH), 256>>>(k, kp);
    pack_v <<<dim3(48, 1, HH), 256>>>(v, vp);

    // 1) M = q^T k    (TA KM, !TB KM) -> KM-packed, round
    gemm_bulk<0, 0, true, false, 2, true><<<dim3(6, 6, HH), 256>>>(
        qp, kp, Mp, 48, DD, 48, 6L * 48 * 2176, 0, 0, 0);

    // 2) A = x M      (XM, KM) -> XM-packed, round
    gemm_bulk<1, 2, false, false, 1, true><<<dim3(6, 8, BB * HH), 256>>>(
        xp, Mp, Ap, 48, DD, 48, 8L * 48 * 2560, 0, 0, 0);

    // 3) S = A x^T    (XM, XM-TB) -> XM-packed, no round (softmax rounds)
    gemm_bulk<0, 1, false, true, 1, false><<<dim3(8, 8, BB * HH), 256>>>(
        Ap, xp, Sp, 48, LL, 64, 8L * 64 * 2560, 0, 0, 0);

    // 4) softmax rows of packed S
    softmax_p<<<dim3(BB * HH * LL), 256>>>(Sp);

    // 5) Vt = x v^T   (XM, XM-TB) -> KM-packed, round
    gemm_bulk<1, 2, false, true, 2, true><<<dim3(1, 8, BB * HH), 256>>>(
        xp, vp, Vtp, 48, DHH, 64, 64L * 2176, 0, 0, 0);

    // 6) out = S Vt   (XM, KM) -> plain row-major, per-head column offset
    gemm_bulk<0, 0, false, false, 0, false><<<dim3(1, 8, BB * HH), 256>>>(
        Sp, Vtp, out, 64, DHH, 0, 0, (long)LL * DD, DHH, DD);
}

// round 7
// speedup vs baseline: 1.3775x; 1.1329x over previous
#include <cuda_runtime.h>
#include <cstdint>

#define BB 4
#define LL 1024
#define DD 768
#define HH 12
#define DHH 64

// Packed scratch: XM tiles, k-contiguous. 128-row tile = 128 x 36 floats
// (32 data + 4 pad) = 18432B; 64-row tile = 64 x 36 = 9216B.
// Element (r, kk) at r*36 + kk.
__device__ __align__(1024) float g_xp [(size_t)BB * 8 * 24 * 4608];      // x   rows=l, k=d
__device__ __align__(1024) float g_qp [(size_t)HH * 6 * 24 * 4608];      // q^T rows=d, k=c
__device__ __align__(1024) float g_kp [(size_t)HH * 6 * 24 * 4608];      // k^T rows=e, k=c
__device__ __align__(1024) float g_vp [(size_t)HH * 24 * 2304];          // v   rows=j(64), k=d
__device__ __align__(1024) float g_Mp [(size_t)HH * 6 * 24 * 4608];      // M^T rows=e, k=d
__device__ __align__(1024) float g_Ap [(size_t)BB * HH * 8 * 24 * 4608]; // A   rows=l, k=e
__device__ __align__(1024) float g_Sp [(size_t)BB * HH * 8 * 32 * 4608]; // S   rows=l, k=m
__device__ __align__(1024) float g_Vtp[(size_t)BB * HH * 32 * 2304];     // Vt  rows=j(64), k=l

__device__ __forceinline__ unsigned f2tf(float x) {
    unsigned u; asm("cvt.rna.tf32.f32 %0, %1;" : "=r"(u) : "f"(x)); return u;
}
__device__ __forceinline__ float rtf(float x) { return __uint_as_float(f2tf(x)); }

__device__ __forceinline__ void mma_tf32(float* c, const unsigned* a, const unsigned* b) {
    asm volatile(
        "mma.sync.aligned.m16n8k8.row.col.f32.tf32.tf32.f32 "
        "{%0,%1,%2,%3}, {%4,%5,%6,%7}, {%8,%9}, {%0,%1,%2,%3};"
        : "+f"(c[0]), "+f"(c[1]), "+f"(c[2]), "+f"(c[3])
        : "r"(a[0]), "r"(a[1]), "r"(a[2]), "r"(a[3]), "r"(b[0]), "r"(b[1]));
}

__device__ __forceinline__ uint32_t sa32(const void* p) {
    return (uint32_t)__cvta_generic_to_shared(p);
}
__device__ __forceinline__ void bulk_g2s(uint32_t dst, const float* src,
                                         uint32_t bytes, uint32_t mbar) {
    asm volatile(
        "cp.async.bulk.shared::cluster.global.mbarrier::complete_tx::bytes [%0], [%1], %2, [%3];"
        :: "r"(dst), "l"(src), "r"(bytes), "r"(mbar) : "memory");
}
__device__ __forceinline__ void bar_wait(uint32_t mbar, unsigned parity) {
    asm volatile(
        "{\n\t.reg .pred P;\n\t"
        "W_%=:\n\t"
        "mbarrier.try_wait.parity.acquire.cta.shared::cta.b64 P, [%0], %1, 0x989680;\n\t"
        "@P bra D_%=;\n\t"
        "bra W_%=;\n\t"
        "D_%=:\n\t}"
        :: "r"(mbar), "r"(parity) : "memory");
}
#define MBAR_INIT(a, c) \
    asm volatile("mbarrier.init.shared.b64 [%0], %1;" :: "r"(a), "r"(c) : "memory")
#define MBAR_TX(a, b) \
    asm volatile("mbarrier.arrive.expect_tx.shared.b64 _, [%0], %1;" :: "r"(a), "r"(b) : "memory")

// ---------------------------------------------------------------------------
// Bulk-fed legacy-HMMA tf32 GEMM on packed XM tiles.
//  C[m,n] = sum_k A[m,k] * B[n,k].  Block 128 x BROWS x 32, 2-stage ring.
//  AZ/BZ: batch mapping 0:z 1:z/HH 2:z%HH.
//  EPI: 0 plain fp32 rows (ldc, +(z%HH)*64 col offset)
//       1 XM tiles rows=m (cNK = n-chunks per row-tile)
//       2 XM tiles rows=n (ETR rows per tile; transposed store)
// ---------------------------------------------------------------------------
template<int AZ, int BZ, int BROWS, int EPI, int ETR, bool RND>
__global__ __launch_bounds__(256, 2)
void gemm_x(const float* __restrict__ Apk, const float* __restrict__ Bpk,
            float* __restrict__ Cg, int nkt, int cNK, long czs, long cs1, int ldc)
{
    constexpr int BTF = BROWS * 36;                 // B tile floats
    constexpr uint32_t ABYT = 18432, BBYT = BTF * 4;
    constexpr int STAGE = 4608 + BTF;               // floats per stage
    constexpr int NT = BROWS / 32;                  // n-subtiles per warp

    extern __shared__ __align__(16) float smem[];
    const uint32_t mb0 = sa32(&smem[0]);            // 2 mbarriers in first 16B
    float* tiles = smem + 256;                      // 1024B offset

    const int z = blockIdx.z;
    const long zA = (AZ == 1) ? z / HH : (AZ == 2 ? z % HH : z);
    const long zB = (BZ == 1) ? z / HH : (BZ == 2 ? z % HH : z);
    const float* Abase = Apk + ((zA * gridDim.y + blockIdx.y) * (long)nkt) * 4608;
    const float* Bbase = Bpk + ((zB * gridDim.x + blockIdx.x) * (long)nkt) * BTF;

    const int tid = threadIdx.x;
    const int lane = tid & 31;
    const int wid = tid >> 5;
    const int wm = (wid & 1) * 64;                  // 2 warps in M
    const int wn = (wid >> 1) * (BROWS / 4);        // 4 warps in N
    const int lm = lane >> 2;                       // 0..7
    const int lk = lane & 3;                        // 0..3
    const int m0 = blockIdx.y * 128;
    const int n0 = blockIdx.x * BROWS;

    float acc[4][NT][4];
    #pragma unroll
    for (int i = 0; i < 4; i++)
        #pragma unroll
        for (int j = 0; j < NT; j++)
            #pragma unroll
            for (int r = 0; r < 4; r++) acc[i][j][r] = 0.f;

    if (tid == 0) { MBAR_INIT(mb0, 1); MBAR_INIT(mb0 + 8, 1); }
    __syncthreads();

    auto issue = [&](int buf, int kt) {
        const uint32_t m = mb0 + 8 * buf;
        MBAR_TX(m, ABYT + BBYT);
        bulk_g2s(sa32(tiles + buf * STAGE), Abase + (long)kt * 4608, ABYT, m);
        bulk_g2s(sa32(tiles + buf * STAGE + 4608), Bbase + (long)kt * BTF, BBYT, m);
    };
    if (tid == 0) { issue(0, 0); issue(1, 1); }

    auto compute = [&](int buf) {
        const float* __restrict__ Ab = tiles + buf * STAGE;
        const float* __restrict__ Bb = Ab + 4608;
        #pragma unroll
        for (int ks = 0; ks < 4; ks++) {
            const int r1 = ks * 8 + lk, r2 = r1 + 4;
            unsigned a[4][4], b[NT][2];
            #pragma unroll
            for (int mt = 0; mt < 4; mt++) {
                const int mr = wm + mt * 16 + lm;
                a[mt][0] = __float_as_uint(Ab[mr * 36 + r1]);
                a[mt][1] = __float_as_uint(Ab[(mr + 8) * 36 + r1]);
                a[mt][2] = __float_as_uint(Ab[mr * 36 + r2]);
                a[mt][3] = __float_as_uint(Ab[(mr + 8) * 36 + r2]);
            }
            #pragma unroll
            for (int nt = 0; nt < NT; nt++) {
                const int nc = wn + nt * 8 + lm;
                b[nt][0] = __float_as_uint(Bb[nc * 36 + r1]);
                b[nt][1] = __float_as_uint(Bb[nc * 36 + r2]);
            }
            #pragma unroll
            for (int mt = 0; mt < 4; mt++)
                #pragma unroll
                for (int nt = 0; nt < NT; nt++)
                    mma_tf32(acc[mt][nt], a[mt], b[nt]);
        }
    };

    unsigned ph[2] = {0, 0};
    for (int t = 0; t < nkt; t++) {
        const int buf = t & 1;
        bar_wait(mb0 + 8 * buf, ph[buf]);
        ph[buf] ^= 1;
        compute(buf);
        __syncthreads();
        if (t + 2 < nkt && tid == 0) issue(buf, t + 2);
    }

    // ---- epilogue ----
    #pragma unroll
    for (int mt = 0; mt < 4; mt++) {
        const int rl = wm + mt * 16 + lm;           // local row (m)
        const int rg = m0 + rl;
        #pragma unroll
        for (int nt = 0; nt < NT; nt++) {
            const int cl = wn + nt * 8 + 2 * lk;    // local col (n)
            const int cg = n0 + cl;
            float v0 = acc[mt][nt][0], v1 = acc[mt][nt][1];
            float v2 = acc[mt][nt][2], v3 = acc[mt][nt][3];
            if (RND) { v0 = rtf(v0); v1 = rtf(v1); v2 = rtf(v2); v3 = rtf(v3); }
            if (EPI == 0) {
                float* C = Cg + (long)(z / HH) * cs1 + (long)(z % HH) * 64;
                *(float2*)&C[(long)rg * ldc + cg]       = make_float2(v0, v1);
                *(float2*)&C[(long)(rg + 8) * ldc + cg] = make_float2(v2, v3);
            } else if (EPI == 1) {
                float* zb = Cg + (long)z * czs + (long)blockIdx.y * cNK * 4608
                          + (long)(cg >> 5) * 4608;
                *(float2*)&zb[rl * 36 + (cl & 31)]       = make_float2(v0, v1);
                *(float2*)&zb[(rl + 8) * 36 + (cl & 31)] = make_float2(v2, v3);
            } else {
                float* zb = Cg + (long)z * czs
                          + (long)blockIdx.x * cNK * (ETR * 36)
                          + (long)(rg >> 5) * (ETR * 36);
                const int rr = rg & 31;
                zb[(cg & (ETR - 1)) * 36 + rr]           = v0;
                zb[((cg + 1) & (ETR - 1)) * 36 + rr]     = v1;
                zb[(cg & (ETR - 1)) * 36 + rr + 8]       = v2;
                zb[((cg + 1) & (ETR - 1)) * 36 + rr + 8] = v3;
            }
        }
    }
}

// ---------------------------------------------------------------------------
// Pack kernels: tf32-round inputs into XM stride-36 tiles.
// ---------------------------------------------------------------------------
__global__ void pack_x(const float* __restrict__ x, float* __restrict__ xp) {
    // grid (24 kt, 8 lt, 4 b)
    float* blob = xp + (((long)blockIdx.z * 8 + blockIdx.y) * 24 + blockIdx.x) * 4608;
    const float* src = x + ((long)(blockIdx.z * LL + blockIdx.y * 128)) * DD + blockIdx.x * 32;
    #pragma unroll
    for (int i = 0; i < 4; i++) {
        const int s = threadIdx.x + i * 256;
        const int row = s >> 3, c4 = (s & 7) << 2;
        float4 v = *(const float4*)&src[(long)row * DD + c4];
        v.x = rtf(v.x); v.y = rtf(v.y); v.z = rtf(v.z); v.w = rtf(v.w);
        *(float4*)&blob[row * 36 + c4] = v;
    }
}
__global__ void pack_qk(const float* __restrict__ in, float* __restrict__ op) {
    // grid (24 kt(c), 6 xt, 12 h): transpose in[h,c,x] -> tiles rows=x, k=c
    float* blob = op + (((long)blockIdx.z * 6 + blockIdx.y) * 24 + blockIdx.x) * 4608;
    const float* src = in + ((long)blockIdx.z * DD + blockIdx.x * 32) * DD + blockIdx.y * 128;
    #pragma unroll
    for (int i = 0; i < 4; i++) {
        const int s = threadIdx.x + i * 256;
        const int c = s >> 5, x0 = (s & 31) << 2;
        float4 v = *(const float4*)&src[(long)c * DD + x0];
        blob[(x0 + 0) * 36 + c] = rtf(v.x);
        blob[(x0 + 1) * 36 + c] = rtf(v.y);
        blob[(x0 + 2) * 36 + c] = rtf(v.z);
        blob[(x0 + 3) * 36 + c] = rtf(v.w);
    }
}
__global__ void pack_v(const float* __restrict__ v, float* __restrict__ vp) {
    // grid (24 kt, 12 h): 64-row tiles rows=j, k=d
    float* blob = vp + ((long)blockIdx.y * 24 + blockIdx.x) * 2304;
    const float* src = v + (long)blockIdx.y * DHH * DD + blockIdx.x * 32;
    #pragma unroll
    for (int i = 0; i < 2; i++) {
        const int s = threadIdx.x + i * 256;
        const int row = s >> 3, c4 = (s & 7) << 2;
        float4 w = *(const float4*)&src[(long)row * DD + c4];
        w.x = rtf(w.x); w.y = rtf(w.y); w.z = rtf(w.z); w.w = rtf(w.w);
        *(float4*)&blob[row * 36 + c4] = w;
    }
}

// ---------------------------------------------------------------------------
// Row softmax on XM-packed S (in place), float4 path, tf32-rounded output.
// ---------------------------------------------------------------------------
__global__ void softmax_p(float* __restrict__ Sp) {
    const int z = blockIdx.x >> 10;
    const int l = blockIdx.x & 1023;
    float* base = Sp + (long)z * (8L * 32 * 4608) + (long)(l >> 7) * (32 * 4608)
                + (l & 127) * 36;
    const int tid = threadIdx.x;
    const int c4 = tid << 2;                        // 4 cols per thread
    float* p = base + (c4 >> 5) * 4608 + (c4 & 31);
    __shared__ float red[8];

    float4 v = *(float4*)p;
    float vmax = fmaxf(fmaxf(v.x, v.y), fmaxf(v.z, v.w));
    #pragma unroll
    for (int o = 16; o > 0; o >>= 1) vmax = fmaxf(vmax, __shfl_xor_sync(~0u, vmax, o));
    if ((tid & 31) == 0) red[tid >> 5] = vmax;
    __syncthreads();
    if (tid < 32) {
        float w = (tid < 8) ? red[tid] : -1e30f;
        #pragma unroll
        for (int o = 4; o > 0; o >>= 1) w = fmaxf(w, __shfl_xor_sync(~0u, w, o));
        if (tid == 0) red[0] = w;
    }
    __syncthreads();
    vmax = red[0];
    __syncthreads();

    v.x = __expf(v.x - vmax); v.y = __expf(v.y - vmax);
    v.z = __expf(v.z - vmax); v.w = __expf(v.w - vmax);
    float s = v.x + v.y + v.z + v.w;
    #pragma unroll
    for (int o = 16; o > 0; o >>= 1) s += __shfl_xor_sync(~0u, s, o);
    if ((tid & 31) == 0) red[tid >> 5] = s;
    __syncthreads();
    if (tid < 32) {
        float w = (tid < 8) ? red[tid] : 0.f;
        #pragma unroll
        for (int o = 4; o > 0; o >>= 1) w += __shfl_xor_sync(~0u, w, o);
        if (tid == 0) red[0] = w;
    }
    __syncthreads();
    const float inv = 1.0f / red[0];
    v.x = rtf(v.x * inv); v.y = rtf(v.y * inv);
    v.z = rtf(v.z * inv); v.w = rtf(v.w * inv);
    *(float4*)p = v;
}

// ---------------------------------------------------------------------------
extern "C" void kernel_launch(void* const* d_in, const int* in_sizes, int n_in,
                              void* d_out, int out_size)
{
    const float* x = (const float*)d_in[0];
    const float* k = (const float*)d_in[1];
    const float* q = (const float*)d_in[2];
    const float* v = (const float*)d_in[3];
    float* out = (float*)d_out;

    float *xp, *qp, *kp, *vp, *Mp, *Ap, *Sp, *Vtp;
    cudaGetSymbolAddress((void**)&xp, g_xp);
    cudaGetSymbolAddress((void**)&qp, g_qp);
    cudaGetSymbolAddress((void**)&kp, g_kp);
    cudaGetSymbolAddress((void**)&vp, g_vp);
    cudaGetSymbolAddress((void**)&Mp, g_Mp);
    cudaGetSymbolAddress((void**)&Ap, g_Ap);
    cudaGetSymbolAddress((void**)&Sp, g_Sp);
    cudaGetSymbolAddress((void**)&Vtp, g_Vtp);

    const int SM128 = 1024 + 2 * (18432 + 18432);   // 74752
    const int SM64  = 1024 + 2 * (18432 + 9216);    // 56320

    auto* G1 = gemm_x<0, 0, 128, 2, 128, true>;
    auto* G2 = gemm_x<1, 2, 128, 1, 0, true>;
    auto* G3 = gemm_x<0, 1, 128, 1, 0, false>;
    auto* G5 = gemm_x<1, 2, 64, 2, 64, true>;
    auto* G6 = gemm_x<0, 0, 64, 0, 0, false>;
    cudaFuncSetAttribute(G1, cudaFuncAttributeMaxDynamicSharedMemorySize, SM128);
    cudaFuncSetAttribute(G2, cudaFuncAttributeMaxDynamicSharedMemorySize, SM128);
    cudaFuncSetAttribute(G3, cudaFuncAttributeMaxDynamicSharedMemorySize, SM128);
    cudaFuncSetAttribute(G5, cudaFuncAttributeMaxDynamicSharedMemorySize, SM64);
    cudaFuncSetAttribute(G6, cudaFuncAttributeMaxDynamicSharedMemorySize, SM64);

    // 0) pack inputs (tf32-rounded)
    pack_x <<<dim3(24, 8, BB), 256>>>(x, xp);
    pack_qk<<<dim3(24, 6, HH), 256>>>(q, qp);
    pack_qk<<<dim3(24, 6, HH), 256>>>(k, kp);
    pack_v <<<dim3(24, HH), 256>>>(v, vp);

    // 1) M^T[e,d] = sum_c q[c,d] k[c,e]  (A=q^T rows=d, B=k^T rows=e) -> EPI2
    G1<<<dim3(6, 6, HH), 256, SM128>>>(qp, kp, Mp, 24, 24, 6L * 24 * 4608, 0, 0);

    // 2) A[l,e] = sum_d x[l,d] M^T[e,d]  -> EPI1 rows=l
    G2<<<dim3(6, 8, BB * HH), 256, SM128>>>(xp, Mp, Ap, 24, 24, 8L * 24 * 4608, 0, 0);

    // 3) S[l,m] = sum_e A[l,e] x[m,e]    -> EPI1 rows=l (softmax rounds)
    G3<<<dim3(8, 8, BB * HH), 256, SM128>>>(Ap, xp, Sp, 24, 32, 8L * 32 * 4608, 0, 0);

    // 4) softmax over m
    softmax_p<<<dim3(BB * HH * LL), 256>>>(Sp);

    // 5) Vt[j,l] = sum_d x[l,d] v[j,d]   -> EPI2 64-row tiles rows=j
    G5<<<dim3(1, 8, BB * HH), 256, SM64>>>(xp, vp, Vtp, 24, 32, 32L * 2304, 0, 0);

    // 6) out[l, h*64+j] = sum_m S[l,m] Vt[j,m->l]  -> plain fp32
    G6<<<dim3(1, 8, BB * HH), 256, SM64>>>(Sp, Vtp, out, 32, 0, 0, (long)LL * DD, DD);
}

// round 8
// speedup vs baseline: 2.1558x; 1.5650x over previous
#include <cuda_runtime.h>
#include <cuda_fp16.h>
#include <cstdint>

#define BB 4
#define LL 1024
#define DD 768
#define HH 12
#define DHH 64

// Packed fp16 scratch: XM tiles, k-contiguous, k-chunks of 64.
//   128-row tile = 128 x 72 halfs (64 data + 8 pad) = 18432B
//   64-row tile  =  64 x 72 halfs = 9216B
// Element (r, kk) at r*72 + kk.
#define TH128 9216   // halfs per 128-row tile
#define TH64  4608   // halfs per 64-row tile
__device__ __align__(1024) __half g_xp [(size_t)BB * 8 * 12 * TH128];      // x   rows=l, k=d
__device__ __align__(1024) __half g_qp [(size_t)HH * 6 * 12 * TH128];      // q^T rows=d, k=c
__device__ __align__(1024) __half g_kp [(size_t)HH * 6 * 12 * TH128];      // k^T rows=e, k=c
__device__ __align__(1024) __half g_vp [(size_t)HH * 12 * TH64];           // v   rows=j, k=d
__device__ __align__(1024) __half g_Mp [(size_t)HH * 6 * 12 * TH128];      // M^T rows=e, k=d
__device__ __align__(1024) __half g_Ap [(size_t)BB * HH * 8 * 12 * TH128]; // A   rows=l, k=e
__device__ __align__(1024) __half g_Sp [(size_t)BB * HH * 8 * 16 * TH128]; // S   rows=l, k=m
__device__ __align__(1024) __half g_Vtp[(size_t)BB * HH * 16 * TH64];      // Vt  rows=j, k=l

__device__ __forceinline__ void mma_f16(float* c, const unsigned* a, const unsigned* b) {
    asm volatile(
        "mma.sync.aligned.m16n8k16.row.col.f32.f16.f16.f32 "
        "{%0,%1,%2,%3}, {%4,%5,%6,%7}, {%8,%9}, {%0,%1,%2,%3};"
        : "+f"(c[0]), "+f"(c[1]), "+f"(c[2]), "+f"(c[3])
        : "r"(a[0]), "r"(a[1]), "r"(a[2]), "r"(a[3]), "r"(b[0]), "r"(b[1]));
}

__device__ __forceinline__ uint32_t sa32(const void* p) {
    return (uint32_t)__cvta_generic_to_shared(p);
}
__device__ __forceinline__ void bulk_g2s(uint32_t dst, const void* src,
                                         uint32_t bytes, uint32_t mbar) {
    asm volatile(
        "cp.async.bulk.shared::cluster.global.mbarrier::complete_tx::bytes [%0], [%1], %2, [%3];"
        :: "r"(dst), "l"(src), "r"(bytes), "r"(mbar) : "memory");
}
__device__ __forceinline__ void bar_wait(uint32_t mbar, unsigned parity) {
    asm volatile(
        "{\n\t.reg .pred P;\n\t"
        "W_%=:\n\t"
        "mbarrier.try_wait.parity.acquire.cta.shared::cta.b64 P, [%0], %1, 0x989680;\n\t"
        "@P bra D_%=;\n\t"
        "bra W_%=;\n\t"
        "D_%=:\n\t}"
        :: "r"(mbar), "r"(parity) : "memory");
}
#define MBAR_INIT(a, c) \
    asm volatile("mbarrier.init.shared.b64 [%0], %1;" :: "r"(a), "r"(c) : "memory")
#define MBAR_TX(a, b) \
    asm volatile("mbarrier.arrive.expect_tx.shared.b64 _, [%0], %1;" :: "r"(a), "r"(b) : "memory")

// ---------------------------------------------------------------------------
// Bulk-fed fp16 HMMA GEMM on packed XM tiles (fp32 accumulate).
//  C[m,n] = sum_k A[m,k] * B[n,k].  Block 128 x BROWS x 64 per stage, 2 stages.
//  AZ/BZ: batch mapping 0:z 1:z/HH 2:z%HH.
//  EPI: 0 plain fp32 (ldc, +(z%HH)*64 col offset)
//       1 fp16 XM tiles rows=m (cNK = k-chunks per output row-tile)
//       2 fp16 XM tiles rows=n, ETR rows/tile (transposed store)
// ---------------------------------------------------------------------------
template<int AZ, int BZ, int BROWS, int EPI, int ETR>
__global__ __launch_bounds__(256, 2)
void gemm_h(const __half* __restrict__ Apk, const __half* __restrict__ Bpk,
            void* __restrict__ Cg, int nkt, int cNK, long czs, long cs1, int ldc)
{
    constexpr int BTH = BROWS * 72;                 // B tile halfs
    constexpr uint32_t ABYT = TH128 * 2, BBYT = BTH * 2;
    constexpr int STAGE = TH128 + BTH;              // halfs per stage
    constexpr int NT = BROWS / 32;

    extern __shared__ __align__(16) __half smem[];
    const uint32_t mb0 = sa32(&smem[0]);
    __half* tiles = smem + 512;                     // 1024B offset

    const int z = blockIdx.z;
    const long zA = (AZ == 1) ? z / HH : (AZ == 2 ? z % HH : z);
    const long zB = (BZ == 1) ? z / HH : (BZ == 2 ? z % HH : z);
    const __half* Abase = Apk + ((zA * gridDim.y + blockIdx.y) * (long)nkt) * TH128;
    const __half* Bbase = Bpk + ((zB * gridDim.x + blockIdx.x) * (long)nkt) * BTH;

    const int tid = threadIdx.x;
    const int lane = tid & 31;
    const int wid = tid >> 5;
    const int wm = (wid & 1) * 64;
    const int wn = (wid >> 1) * (BROWS / 4);
    const int lm = lane >> 2;
    const int lk = lane & 3;
    const int m0 = blockIdx.y * 128;
    const int n0 = blockIdx.x * BROWS;

    float acc[4][NT][4];
    #pragma unroll
    for (int i = 0; i < 4; i++)
        #pragma unroll
        for (int j = 0; j < NT; j++)
            #pragma unroll
            for (int r = 0; r < 4; r++) acc[i][j][r] = 0.f;

    if (tid == 0) { MBAR_INIT(mb0, 1); MBAR_INIT(mb0 + 8, 1); }
    __syncthreads();

    auto issue = [&](int buf, int kt) {
        const uint32_t m = mb0 + 8 * buf;
        MBAR_TX(m, ABYT + BBYT);
        bulk_g2s(sa32(tiles + buf * STAGE), Abase + (long)kt * TH128, ABYT, m);
        bulk_g2s(sa32(tiles + buf * STAGE + TH128), Bbase + (long)kt * BTH, BBYT, m);
    };
    if (tid == 0) { issue(0, 0); issue(1, 1); }

    auto compute = [&](int buf) {
        const __half* __restrict__ Ab = tiles + buf * STAGE;
        const __half* __restrict__ Bb = Ab + TH128;
        #pragma unroll
        for (int s = 0; s < 4; s++) {               // 4 x k16 per 64-k stage
            const int kb = s * 16 + 2 * lk;
            unsigned a[4][4], b[NT][2];
            #pragma unroll
            for (int mt = 0; mt < 4; mt++) {
                const int mr = wm + mt * 16 + lm;
                a[mt][0] = *(const unsigned*)&Ab[mr * 72 + kb];
                a[mt][1] = *(const unsigned*)&Ab[(mr + 8) * 72 + kb];
                a[mt][2] = *(const unsigned*)&Ab[mr * 72 + kb + 8];
                a[mt][3] = *(const unsigned*)&Ab[(mr + 8) * 72 + kb + 8];
            }
            #pragma unroll
            for (int nt = 0; nt < NT; nt++) {
                const int nc = wn + nt * 8 + lm;
                b[nt][0] = *(const unsigned*)&Bb[nc * 72 + kb];
                b[nt][1] = *(const unsigned*)&Bb[nc * 72 + kb + 8];
            }
            #pragma unroll
            for (int mt = 0; mt < 4; mt++)
                #pragma unroll
                for (int nt = 0; nt < NT; nt++)
                    mma_f16(acc[mt][nt], a[mt], b[nt]);
        }
    };

    unsigned ph[2] = {0, 0};
    for (int t = 0; t < nkt; t++) {
        const int buf = t & 1;
        bar_wait(mb0 + 8 * buf, ph[buf]);
        ph[buf] ^= 1;
        compute(buf);
        __syncthreads();
        if (t + 2 < nkt && tid == 0) issue(buf, t + 2);
    }

    // ---- epilogue ----
    #pragma unroll
    for (int mt = 0; mt < 4; mt++) {
        const int rl = wm + mt * 16 + lm;
        const int rg = m0 + rl;
        #pragma unroll
        for (int nt = 0; nt < NT; nt++) {
            const int cl = wn + nt * 8 + 2 * lk;
            const int cg = n0 + cl;
            const float v0 = acc[mt][nt][0], v1 = acc[mt][nt][1];
            const float v2 = acc[mt][nt][2], v3 = acc[mt][nt][3];
            if (EPI == 0) {
                float* C = (float*)Cg + (long)(z / HH) * cs1 + (long)(z % HH) * 64;
                *(float2*)&C[(long)rg * ldc + cg]       = make_float2(v0, v1);
                *(float2*)&C[(long)(rg + 8) * ldc + cg] = make_float2(v2, v3);
            } else if (EPI == 1) {
                __half* zb = (__half*)Cg + (long)z * czs
                           + ((long)blockIdx.y * cNK + (cg >> 6)) * TH128;
                const int co = cl & 63;
                *(__half2*)&zb[rl * 72 + co]       = __float22half2_rn(make_float2(v0, v1));
                *(__half2*)&zb[(rl + 8) * 72 + co] = __float22half2_rn(make_float2(v2, v3));
            } else {
                __half* zb = (__half*)Cg + (long)z * czs
                           + ((long)(cg / ETR) * cNK + (rg >> 6)) * (ETR * 72);
                const int rr = rg & 63;
                zb[(cg & (ETR - 1)) * 72 + rr]           = __float2half_rn(v0);
                zb[((cg + 1) & (ETR - 1)) * 72 + rr]     = __float2half_rn(v1);
                zb[(cg & (ETR - 1)) * 72 + rr + 8]       = __float2half_rn(v2);
                zb[((cg + 1) & (ETR - 1)) * 72 + rr + 8] = __float2half_rn(v3);
            }
        }
    }
}

// ---------------------------------------------------------------------------
// Pack kernels: fp32 -> fp16 XM stride-72 tiles.
// ---------------------------------------------------------------------------
__global__ void pack_x(const float* __restrict__ x, __half* __restrict__ xp) {
    // grid (12 kt, 8 lt, 4 b)
    __half* blob = xp + (((long)blockIdx.z * 8 + blockIdx.y) * 12 + blockIdx.x) * TH128;
    const float* src = x + ((long)(blockIdx.z * LL + blockIdx.y * 128)) * DD + blockIdx.x * 64;
    #pragma unroll
    for (int i = 0; i < 8; i++) {
        const int s = threadIdx.x + i * 256;        // 2048 quads
        const int row = s >> 4, c4 = (s & 15) << 2;
        const float4 v = *(const float4*)&src[(long)row * DD + c4];
        *(__half2*)&blob[row * 72 + c4]     = __float22half2_rn(make_float2(v.x, v.y));
        *(__half2*)&blob[row * 72 + c4 + 2] = __float22half2_rn(make_float2(v.z, v.w));
    }
}
__global__ void pack_qk(const float* __restrict__ in, __half* __restrict__ op) {
    // grid (12 kt(c), 6 xt, 12 h): transpose in[h,c,x] -> tiles rows=x, k=c
    __half* blob = op + (((long)blockIdx.z * 6 + blockIdx.y) * 12 + blockIdx.x) * TH128;
    const float* src = in + ((long)blockIdx.z * DD + blockIdx.x * 64) * DD + blockIdx.y * 128;
    #pragma unroll
    for (int i = 0; i < 8; i++) {
        const int s = threadIdx.x + i * 256;        // 2048 quads
        const int c = s >> 5, x0 = (s & 31) << 2;
        const float4 v = *(const float4*)&src[(long)c * DD + x0];
        blob[(x0 + 0) * 72 + c] = __float2half_rn(v.x);
        blob[(x0 + 1) * 72 + c] = __float2half_rn(v.y);
        blob[(x0 + 2) * 72 + c] = __float2half_rn(v.z);
        blob[(x0 + 3) * 72 + c] = __float2half_rn(v.w);
    }
}
__global__ void pack_v(const float* __restrict__ v, __half* __restrict__ vp) {
    // grid (12 kt, 12 h): 64-row tiles rows=j, k=d
    __half* blob = vp + ((long)blockIdx.y * 12 + blockIdx.x) * TH64;
    const float* src = v + (long)blockIdx.y * DHH * DD + blockIdx.x * 64;
    #pragma unroll
    for (int i = 0; i < 4; i++) {
        const int s = threadIdx.x + i * 256;        // 1024 quads
        const int row = s >> 4, c4 = (s & 15) << 2;
        const float4 w = *(const float4*)&src[(long)row * DD + c4];
        *(__half2*)&blob[row * 72 + c4]     = __float22half2_rn(make_float2(w.x, w.y));
        *(__half2*)&blob[row * 72 + c4 + 2] = __float22half2_rn(make_float2(w.z, w.w));
    }
}

// ---------------------------------------------------------------------------
// Row softmax on fp16 XM-packed S (in place). fp32 internal math.
// ---------------------------------------------------------------------------
__global__ void softmax_p(__half* __restrict__ Sp) {
    const int z = blockIdx.x >> 10;
    const int l = blockIdx.x & 1023;
    __half* base = Sp + (long)(z * 8 + (l >> 7)) * (16L * TH128) + (l & 127) * 72;
    const int tid = threadIdx.x;
    const int c4 = tid << 2;                        // 4 cols per thread
    __half* p = base + (c4 >> 6) * TH128 + (c4 & 63);
    __shared__ float red[8];

    const __half2 h0 = *(__half2*)p;
    const __half2 h1 = *(__half2*)(p + 2);
    float2 f0 = __half22float2(h0), f1 = __half22float2(h1);
    float vmax = fmaxf(fmaxf(f0.x, f0.y), fmaxf(f1.x, f1.y));
    #pragma unroll
    for (int o = 16; o > 0; o >>= 1) vmax = fmaxf(vmax, __shfl_xor_sync(~0u, vmax, o));
    if ((tid & 31) == 0) red[tid >> 5] = vmax;
    __syncthreads();
    if (tid < 32) {
        float w = (tid < 8) ? red[tid] : -1e30f;
        #pragma unroll
        for (int o = 4; o > 0; o >>= 1) w = fmaxf(w, __shfl_xor_sync(~0u, w, o));
        if (tid == 0) red[0] = w;
    }
    __syncthreads();
    vmax = red[0];
    __syncthreads();

    f0.x = __expf(f0.x - vmax); f0.y = __expf(f0.y - vmax);
    f1.x = __expf(f1.x - vmax); f1.y = __expf(f1.y - vmax);
    float s = f0.x + f0.y + f1.x + f1.y;
    #pragma unroll
    for (int o = 16; o > 0; o >>= 1) s += __shfl_xor_sync(~0u, s, o);
    if ((tid & 31) == 0) red[tid >> 5] = s;
    __syncthreads();
    if (tid < 32) {
        float w = (tid < 8) ? red[tid] : 0.f;
        #pragma unroll
        for (int o = 4; o > 0; o >>= 1) w += __shfl_xor_sync(~0u, w, o);
        if (tid == 0) red[0] = w;
    }
    __syncthreads();
    const float inv = 1.0f / red[0];
    *(__half2*)p       = __float22half2_rn(make_float2(f0.x * inv, f0.y * inv));
    *(__half2*)(p + 2) = __float22half2_rn(make_float2(f1.x * inv, f1.y * inv));
}

// ---------------------------------------------------------------------------
extern "C" void kernel_launch(void* const* d_in, const int* in_sizes, int n_in,
                              void* d_out, int out_size)
{
    const float* x = (const float*)d_in[0];
    const float* k = (const float*)d_in[1];
    const float* q = (const float*)d_in[2];
    const float* v = (const float*)d_in[3];
    float* out = (float*)d_out;

    __half *xp, *qp, *kp, *vp, *Mp, *Ap, *Sp, *Vtp;
    cudaGetSymbolAddress((void**)&xp, g_xp);
    cudaGetSymbolAddress((void**)&qp, g_qp);
    cudaGetSymbolAddress((void**)&kp, g_kp);
    cudaGetSymbolAddress((void**)&vp, g_vp);
    cudaGetSymbolAddress((void**)&Mp, g_Mp);
    cudaGetSymbolAddress((void**)&Ap, g_Ap);
    cudaGetSymbolAddress((void**)&Sp, g_Sp);
    cudaGetSymbolAddress((void**)&Vtp, g_Vtp);

    const int SM128 = 1024 + 2 * (18432 + 18432);   // 74752
    const int SM64  = 1024 + 2 * (18432 + 9216);    // 56320

    auto* G1 = gemm_h<0, 0, 128, 2, 128>;
    auto* G2 = gemm_h<1, 2, 128, 1, 0>;
    auto* G3 = gemm_h<0, 1, 128, 1, 0>;
    auto* G5 = gemm_h<1, 2, 64, 2, 64>;
    auto* G6 = gemm_h<0, 0, 64, 0, 0>;
    cudaFuncSetAttribute(G1, cudaFuncAttributeMaxDynamicSharedMemorySize, SM128);
    cudaFuncSetAttribute(G2, cudaFuncAttributeMaxDynamicSharedMemorySize, SM128);
    cudaFuncSetAttribute(G3, cudaFuncAttributeMaxDynamicSharedMemorySize, SM128);
    cudaFuncSetAttribute(G5, cudaFuncAttributeMaxDynamicSharedMemorySize, SM64);
    cudaFuncSetAttribute(G6, cudaFuncAttributeMaxDynamicSharedMemorySize, SM64);

    // 0) pack inputs (fp16)
    pack_x <<<dim3(12, 8, BB), 256>>>(x, xp);
    pack_qk<<<dim3(12, 6, HH), 256>>>(q, qp);
    pack_qk<<<dim3(12, 6, HH), 256>>>(k, kp);
    pack_v <<<dim3(12, HH), 256>>>(v, vp);

    // 1) M^T[e,d] = sum_c q[c,d] k[c,e]   -> EPI2 rows=e tiles
    G1<<<dim3(6, 6, HH), 256, SM128>>>(qp, kp, Mp, 12, 12, 6L * 12 * TH128, 0, 0);

    // 2) A[l,e] = sum_d x[l,d] M^T[e,d]   -> EPI1 rows=l
    G2<<<dim3(6, 8, BB * HH), 256, SM128>>>(xp, Mp, Ap, 12, 12, 8L * 12 * TH128, 0, 0);

    // 3) S[l,m] = sum_e A[l,e] x[m,e]     -> EPI1 rows=l
    G3<<<dim3(8, 8, BB * HH), 256, SM128>>>(Ap, xp, Sp, 12, 16, 8L * 16 * TH128, 0, 0);

    // 4) softmax over m (fp16 in/out, fp32 math)
    softmax_p<<<dim3(BB * HH * LL), 256>>>(Sp);

    // 5) Vt[j,l] = sum_d x[l,d] v[j,d]    -> EPI2 64-row tiles rows=j
    G5<<<dim3(1, 8, BB * HH), 256, SM64>>>(xp, vp, Vtp, 12, 16, 16L * TH64, 0, 0);

    // 6) out[l, h*64+j] = sum_m S[l,m] Vt[j,m]  -> plain fp32
    G6<<<dim3(1, 8, BB * HH), 256, SM64>>>(Sp, Vtp, out, 16, 0, 0, (long)LL * DD, DD);
}

// round 9
// speedup vs baseline: 2.1753x; 1.0090x over previous
#include <cuda_runtime.h>
#include <cuda_fp16.h>
#include <cstdint>

#define BB 4
#define LL 1024
#define DD 768
#define HH 12
#define DHH 64

// Packed fp16 scratch: XM tiles, k-contiguous, k-chunks of 64.
//   128-row tile = 128 x 72 halfs (64 data + 8 pad) = 18432B
//   64-row tile  =  64 x 72 halfs = 9216B
#define TH128 9216
#define TH64  4608
__device__ __align__(1024) __half g_xp [(size_t)BB * 8 * 12 * TH128];
__device__ __align__(1024) __half g_qp [(size_t)HH * 6 * 12 * TH128];
__device__ __align__(1024) __half g_kp [(size_t)HH * 6 * 12 * TH128];
__device__ __align__(1024) __half g_vp [(size_t)HH * 12 * TH64];
__device__ __align__(1024) __half g_Mp [(size_t)HH * 6 * 12 * TH128];
__device__ __align__(1024) __half g_Ap [(size_t)BB * HH * 8 * 12 * TH128];
__device__ __align__(1024) __half g_Sp [(size_t)BB * HH * 8 * 16 * TH128];
__device__ __align__(1024) __half g_Vtp[(size_t)BB * HH * 16 * TH64];

__device__ __forceinline__ void mma_f16(float* c, const unsigned* a, const unsigned* b) {
    asm volatile(
        "mma.sync.aligned.m16n8k16.row.col.f32.f16.f16.f32 "
        "{%0,%1,%2,%3}, {%4,%5,%6,%7}, {%8,%9}, {%0,%1,%2,%3};"
        : "+f"(c[0]), "+f"(c[1]), "+f"(c[2]), "+f"(c[3])
        : "r"(a[0]), "r"(a[1]), "r"(a[2]), "r"(a[3]), "r"(b[0]), "r"(b[1]));
}
#define LDSM4(r0, r1, r2, r3, addr) \
    asm volatile("ldmatrix.sync.aligned.m8n8.x4.shared.b16 {%0,%1,%2,%3}, [%4];" \
        : "=r"(r0), "=r"(r1), "=r"(r2), "=r"(r3) : "r"(addr))

__device__ __forceinline__ uint32_t sa32(const void* p) {
    return (uint32_t)__cvta_generic_to_shared(p);
}
__device__ __forceinline__ void bulk_g2s(uint32_t dst, const void* src,
                                         uint32_t bytes, uint32_t mbar) {
    asm volatile(
        "cp.async.bulk.shared::cluster.global.mbarrier::complete_tx::bytes [%0], [%1], %2, [%3];"
        :: "r"(dst), "l"(src), "r"(bytes), "r"(mbar) : "memory");
}
__device__ __forceinline__ void bar_wait(uint32_t mbar, unsigned parity) {
    asm volatile(
        "{\n\t.reg .pred P;\n\t"
        "W_%=:\n\t"
        "mbarrier.try_wait.parity.acquire.cta.shared::cta.b64 P, [%0], %1, 0x989680;\n\t"
        "@P bra D_%=;\n\t"
        "bra W_%=;\n\t"
        "D_%=:\n\t}"
        :: "r"(mbar), "r"(parity) : "memory");
}
#define MBAR_INIT(a, c) \
    asm volatile("mbarrier.init.shared.b64 [%0], %1;" :: "r"(a), "r"(c) : "memory")
#define MBAR_TX(a, b) \
    asm volatile("mbarrier.arrive.expect_tx.shared.b64 _, [%0], %1;" :: "r"(a), "r"(b) : "memory")

// ---------------------------------------------------------------------------
// Bulk-fed fp16 HMMA GEMM, ldmatrix fragment loads, 3-stage ring.
//  C[m,n] = sum_k A[m,k]*B[n,k]. Block 128 x BROWS x 64 per stage.
//  EPI: 0 plain fp32; 1 fp16 XM tiles rows=m; 2 fp16 XM tiles rows=n (ETR).
// ---------------------------------------------------------------------------
template<int AZ, int BZ, int BROWS, int EPI, int ETR>
__global__ __launch_bounds__(256, 2)
void gemm_h(const __half* __restrict__ Apk, const __half* __restrict__ Bpk,
            void* __restrict__ Cg, int nkt, int cNK, long czs, long cs1, int ldc)
{
    constexpr int BTH = BROWS * 72;
    constexpr uint32_t ABYT = TH128 * 2, BBYT = BTH * 2;
    constexpr int STAGE = TH128 + BTH;              // halfs per stage
    constexpr int NT = BROWS / 32;

    extern __shared__ __align__(16) __half smem[];
    const uint32_t mb0 = sa32(&smem[0]);            // 3 mbarriers
    __half* tiles = smem + 512;
    const uint32_t tbase = sa32(tiles);

    const int z = blockIdx.z;
    const long zA = (AZ == 1) ? z / HH : (AZ == 2 ? z % HH : z);
    const long zB = (BZ == 1) ? z / HH : (BZ == 2 ? z % HH : z);
    const __half* Abase = Apk + ((zA * gridDim.y + blockIdx.y) * (long)nkt) * TH128;
    const __half* Bbase = Bpk + ((zB * gridDim.x + blockIdx.x) * (long)nkt) * BTH;

    const int tid = threadIdx.x;
    const int lane = tid & 31;
    const int wid = tid >> 5;
    const int wm = (wid & 1) * 64;
    const int wn = (wid >> 1) * (BROWS / 4);
    const int lm = lane >> 2;
    const int lk = lane & 3;
    const int m0 = blockIdx.y * 128;
    const int n0 = blockIdx.x * BROWS;

    // ldmatrix lane address components (bytes, relative to tile base)
    const uint32_t laOff = (uint32_t)((wm + (lane & 7) + ((lane >> 3) & 1) * 8) * 72
                                      + (lane >> 4) * 8) * 2;
    const uint32_t lbOff = (uint32_t)((wn + (lane >> 4) * 8 + (lane & 7)) * 72
                                      + ((lane >> 3) & 1) * 8) * 2;

    float acc[4][NT][4];
    #pragma unroll
    for (int i = 0; i < 4; i++)
        #pragma unroll
        for (int j = 0; j < NT; j++)
            #pragma unroll
            for (int r = 0; r < 4; r++) acc[i][j][r] = 0.f;

    if (tid == 0) {
        MBAR_INIT(mb0, 1); MBAR_INIT(mb0 + 8, 1); MBAR_INIT(mb0 + 16, 1);
    }
    __syncthreads();

    auto issue = [&](int st, int kt) {
        const uint32_t m = mb0 + 8 * st;
        MBAR_TX(m, ABYT + BBYT);
        bulk_g2s(tbase + st * STAGE * 2, Abase + (long)kt * TH128, ABYT, m);
        bulk_g2s(tbase + st * STAGE * 2 + ABYT, Bbase + (long)kt * BTH, BBYT, m);
    };
    if (tid == 0) { issue(0, 0); issue(1, 1); issue(2, 2); }

    auto compute = [&](int st) {
        const uint32_t Abs = tbase + st * STAGE * 2;
        const uint32_t la = Abs + laOff;
        const uint32_t lb = Abs + ABYT + lbOff;
        #pragma unroll
        for (int s = 0; s < 4; s++) {               // 4 x k16 per stage
            const uint32_t off = s * 32;            // 16 halfs
            unsigned a[4][4], b[NT][2];
            #pragma unroll
            for (int mt = 0; mt < 4; mt++)
                LDSM4(a[mt][0], a[mt][1], a[mt][2], a[mt][3], la + off + mt * 2304);
            #pragma unroll
            for (int np = 0; np < NT / 2; np++)
                LDSM4(b[2*np][0], b[2*np][1], b[2*np+1][0], b[2*np+1][1],
                      lb + off + np * 2304);
            #pragma unroll
            for (int mt = 0; mt < 4; mt++)
                #pragma unroll
                for (int nt = 0; nt < NT; nt++)
                    mma_f16(acc[mt][nt], a[mt], b[nt]);
        }
    };

    unsigned ph[3] = {0, 0, 0};
    int st = 0;
    for (int t = 0; t < nkt; t++) {
        bar_wait(mb0 + 8 * st, ph[st]);
        ph[st] ^= 1;
        compute(st);
        __syncthreads();
        if (t + 3 < nkt && tid == 0) issue(st, t + 3);
        st = (st == 2) ? 0 : st + 1;
    }

    // ---- epilogue ----
    #pragma unroll
    for (int mt = 0; mt < 4; mt++) {
        const int rl = wm + mt * 16 + lm;
        const int rg = m0 + rl;
        #pragma unroll
        for (int nt = 0; nt < NT; nt++) {
            const int cl = wn + nt * 8 + 2 * lk;
            const int cg = n0 + cl;
            const float v0 = acc[mt][nt][0], v1 = acc[mt][nt][1];
            const float v2 = acc[mt][nt][2], v3 = acc[mt][nt][3];
            if (EPI == 0) {
                float* C = (float*)Cg + (long)(z / HH) * cs1 + (long)(z % HH) * 64;
                *(float2*)&C[(long)rg * ldc + cg]       = make_float2(v0, v1);
                *(float2*)&C[(long)(rg + 8) * ldc + cg] = make_float2(v2, v3);
            } else if (EPI == 1) {
                __half* zb = (__half*)Cg + (long)z * czs
                           + ((long)blockIdx.y * cNK + (cg >> 6)) * TH128;
                const int co = cl & 63;
                *(__half2*)&zb[rl * 72 + co]       = __float22half2_rn(make_float2(v0, v1));
                *(__half2*)&zb[(rl + 8) * 72 + co] = __float22half2_rn(make_float2(v2, v3));
            } else {
                __half* zb = (__half*)Cg + (long)z * czs
                           + ((long)(cg / ETR) * cNK + (rg >> 6)) * (ETR * 72);
                const int rr = rg & 63;
                zb[(cg & (ETR - 1)) * 72 + rr]           = __float2half_rn(v0);
                zb[((cg + 1) & (ETR - 1)) * 72 + rr]     = __float2half_rn(v1);
                zb[(cg & (ETR - 1)) * 72 + rr + 8]       = __float2half_rn(v2);
                zb[((cg + 1) & (ETR - 1)) * 72 + rr + 8] = __float2half_rn(v3);
            }
        }
    }
}

// ---------------------------------------------------------------------------
// Pack kernels: fp32 -> fp16 XM stride-72 tiles.
// ---------------------------------------------------------------------------
__global__ void pack_x(const float* __restrict__ x, __half* __restrict__ xp) {
    __half* blob = xp + (((long)blockIdx.z * 8 + blockIdx.y) * 12 + blockIdx.x) * TH128;
    const float* src = x + ((long)(blockIdx.z * LL + blockIdx.y * 128)) * DD + blockIdx.x * 64;
    #pragma unroll
    for (int i = 0; i < 8; i++) {
        const int s = threadIdx.x + i * 256;
        const int row = s >> 4, c4 = (s & 15) << 2;
        const float4 v = *(const float4*)&src[(long)row * DD + c4];
        *(__half2*)&blob[row * 72 + c4]     = __float22half2_rn(make_float2(v.x, v.y));
        *(__half2*)&blob[row * 72 + c4 + 2] = __float22half2_rn(make_float2(v.z, v.w));
    }
}
__global__ void pack_qk(const float* __restrict__ in, __half* __restrict__ op) {
    __half* blob = op + (((long)blockIdx.z * 6 + blockIdx.y) * 12 + blockIdx.x) * TH128;
    const float* src = in + ((long)blockIdx.z * DD + blockIdx.x * 64) * DD + blockIdx.y * 128;
    #pragma unroll
    for (int i = 0; i < 8; i++) {
        const int s = threadIdx.x + i * 256;
        const int c = s >> 5, x0 = (s & 31) << 2;
        const float4 v = *(const float4*)&src[(long)c * DD + x0];
        blob[(x0 + 0) * 72 + c] = __float2half_rn(v.x);
        blob[(x0 + 1) * 72 + c] = __float2half_rn(v.y);
        blob[(x0 + 2) * 72 + c] = __float2half_rn(v.z);
        blob[(x0 + 3) * 72 + c] = __float2half_rn(v.w);
    }
}
__global__ void pack_v(const float* __restrict__ v, __half* __restrict__ vp) {
    __half* blob = vp + ((long)blockIdx.y * 12 + blockIdx.x) * TH64;
    const float* src = v + (long)blockIdx.y * DHH * DD + blockIdx.x * 64;
    #pragma unroll
    for (int i = 0; i < 4; i++) {
        const int s = threadIdx.x + i * 256;
        const int row = s >> 4, c4 = (s & 15) << 2;
        const float4 w = *(const float4*)&src[(long)row * DD + c4];
        *(__half2*)&blob[row * 72 + c4]     = __float22half2_rn(make_float2(w.x, w.y));
        *(__half2*)&blob[row * 72 + c4 + 2] = __float22half2_rn(make_float2(w.z, w.w));
    }
}

// ---------------------------------------------------------------------------
// Row softmax on fp16 XM-packed S (in place). fp32 internal math.
// ---------------------------------------------------------------------------
__global__ void softmax_p(__half* __restrict__ Sp) {
    const int z = blockIdx.x >> 10;
    const int l = blockIdx.x & 1023;
    __half* base = Sp + (long)(z * 8 + (l >> 7)) * (16L * TH128) + (l & 127) * 72;
    const int tid = threadIdx.x;
    const int c4 = tid << 2;
    __half* p = base + (c4 >> 6) * TH128 + (c4 & 63);
    __shared__ float red[8];

    const __half2 h0 = *(__half2*)p;
    const __half2 h1 = *(__half2*)(p + 2);
    float2 f0 = __half22float2(h0), f1 = __half22float2(h1);
    float vmax = fmaxf(fmaxf(f0.x, f0.y), fmaxf(f1.x, f1.y));
    #pragma unroll
    for (int o = 16; o > 0; o >>= 1) vmax = fmaxf(vmax, __shfl_xor_sync(~0u, vmax, o));
    if ((tid & 31) == 0) red[tid >> 5] = vmax;
    __syncthreads();
    if (tid < 32) {
        float w = (tid < 8) ? red[tid] : -1e30f;
        #pragma unroll
        for (int o = 4; o > 0; o >>= 1) w = fmaxf(w, __shfl_xor_sync(~0u, w, o));
        if (tid == 0) red[0] = w;
    }
    __syncthreads();
    vmax = red[0];
    __syncthreads();

    f0.x = __expf(f0.x - vmax); f0.y = __expf(f0.y - vmax);
    f1.x = __expf(f1.x - vmax); f1.y = __expf(f1.y - vmax);
    float s = f0.x + f0.y + f1.x + f1.y;
    #pragma unroll
    for (int o = 16; o > 0; o >>= 1) s += __shfl_xor_sync(~0u, s, o);
    if ((tid & 31) == 0) red[tid >> 5] = s;
    __syncthreads();
    if (tid < 32) {
        float w = (tid < 8) ? red[tid] : 0.f;
        #pragma unroll
        for (int o = 4; o > 0; o >>= 1) w += __shfl_xor_sync(~0u, w, o);
        if (tid == 0) red[0] = w;
    }
    __syncthreads();
    const float inv = 1.0f / red[0];
    *(__half2*)p       = __float22half2_rn(make_float2(f0.x * inv, f0.y * inv));
    *(__half2*)(p + 2) = __float22half2_rn(make_float2(f1.x * inv, f1.y * inv));
}

// ---------------------------------------------------------------------------
extern "C" void kernel_launch(void* const* d_in, const int* in_sizes, int n_in,
                              void* d_out, int out_size)
{
    const float* x = (const float*)d_in[0];
    const float* k = (const float*)d_in[1];
    const float* q = (const float*)d_in[2];
    const float* v = (const float*)d_in[3];
    float* out = (float*)d_out;

    __half *xp, *qp, *kp, *vp, *Mp, *Ap, *Sp, *Vtp;
    cudaGetSymbolAddress((void**)&xp, g_xp);
    cudaGetSymbolAddress((void**)&qp, g_qp);
    cudaGetSymbolAddress((void**)&kp, g_kp);
    cudaGetSymbolAddress((void**)&vp, g_vp);
    cudaGetSymbolAddress((void**)&Mp, g_Mp);
    cudaGetSymbolAddress((void**)&Ap, g_Ap);
    cudaGetSymbolAddress((void**)&Sp, g_Sp);
    cudaGetSymbolAddress((void**)&Vtp, g_Vtp);

    const int SM128 = 1024 + 3 * (18432 + 18432);   // 111616
    const int SM64  = 1024 + 3 * (18432 + 9216);    // 83968

    auto* G1 = gemm_h<0, 0, 128, 2, 128>;
    auto* G2 = gemm_h<1, 2, 128, 1, 0>;
    auto* G3 = gemm_h<0, 1, 128, 1, 0>;
    auto* G5 = gemm_h<1, 2, 64, 2, 64>;
    auto* G6 = gemm_h<0, 0, 64, 0, 0>;
    cudaFuncSetAttribute(G1, cudaFuncAttributeMaxDynamicSharedMemorySize, SM128);
    cudaFuncSetAttribute(G2, cudaFuncAttributeMaxDynamicSharedMemorySize, SM128);
    cudaFuncSetAttribute(G3, cudaFuncAttributeMaxDynamicSharedMemorySize, SM128);
    cudaFuncSetAttribute(G5, cudaFuncAttributeMaxDynamicSharedMemorySize, SM64);
    cudaFuncSetAttribute(G6, cudaFuncAttributeMaxDynamicSharedMemorySize, SM64);

    // 0) pack inputs (fp16)
    pack_x <<<dim3(12, 8, BB), 256>>>(x, xp);
    pack_qk<<<dim3(12, 6, HH), 256>>>(q, qp);
    pack_qk<<<dim3(12, 6, HH), 256>>>(k, kp);
    pack_v <<<dim3(12, HH), 256>>>(v, vp);

    // 1) M^T[e,d] = sum_c q[c,d] k[c,e]
    G1<<<dim3(6, 6, HH), 256, SM128>>>(qp, kp, Mp, 12, 12, 6L * 12 * TH128, 0, 0);

    // 2) A[l,e] = sum_d x[l,d] M^T[e,d]
    G2<<<dim3(6, 8, BB * HH), 256, SM128>>>(xp, Mp, Ap, 12, 12, 8L * 12 * TH128, 0, 0);

    // 3) S[l,m] = sum_e A[l,e] x[m,e]
    G3<<<dim3(8, 8, BB * HH), 256, SM128>>>(Ap, xp, Sp, 12, 16, 8L * 16 * TH128, 0, 0);

    // 4) softmax over m
    softmax_p<<<dim3(BB * HH * LL), 256>>>(Sp);

    // 5) Vt[j,l] = sum_d x[l,d] v[j,d]
    G5<<<dim3(1, 8, BB * HH), 256, SM64>>>(xp, vp, Vtp, 12, 16, 16L * TH64, 0, 0);

    // 6) out[l, h*64+j] = sum_m S[l,m] Vt[j,m]
    G6<<<dim3(1, 8, BB * HH), 256, SM64>>>(Sp, Vtp, out, 16, 0, 0, (long)LL * DD, DD);
}

// round 10
// speedup vs baseline: 2.4500x; 1.1263x over previous
#include <cuda_runtime.h>
#include <cuda_fp16.h>
#include <cstdint>

#define BB 4
#define LL 1024
#define DD 768
#define HH 12
#define DHH 64

// Packed fp16 scratch: XM tiles, k-contiguous, k-chunks of 64.
//   128-row tile = 128 x 72 halfs (64 data + 8 pad) = 18432B
//   64-row tile  =  64 x 72 halfs = 9216B
#define TH128 9216
#define TH64  4608
__device__ __align__(1024) __half g_xp [(size_t)BB * 8 * 12 * TH128];
__device__ __align__(1024) __half g_qp [(size_t)HH * 6 * 12 * TH128];
__device__ __align__(1024) __half g_kp [(size_t)HH * 6 * 12 * TH128];
__device__ __align__(1024) __half g_vp [(size_t)HH * 12 * TH64];
__device__ __align__(1024) __half g_Mp [(size_t)HH * 6 * 12 * TH128];
__device__ __align__(1024) __half g_Ap [(size_t)BB * HH * 8 * 12 * TH128];
__device__ __align__(1024) __half g_Sp [(size_t)BB * HH * 8 * 16 * TH128]; // P = exp(S)
__device__ __align__(1024) __half g_Vtp[(size_t)BB * HH * 16 * TH64];
__device__ float g_rsum[(size_t)BB * HH * LL];       // per-row sums of exp(S)

__device__ __forceinline__ void mma_f16(float* c, const unsigned* a, const unsigned* b) {
    asm volatile(
        "mma.sync.aligned.m16n8k16.row.col.f32.f16.f16.f32 "
        "{%0,%1,%2,%3}, {%4,%5,%6,%7}, {%8,%9}, {%0,%1,%2,%3};"
        : "+f"(c[0]), "+f"(c[1]), "+f"(c[2]), "+f"(c[3])
        : "r"(a[0]), "r"(a[1]), "r"(a[2]), "r"(a[3]), "r"(b[0]), "r"(b[1]));
}

__device__ __forceinline__ uint32_t sa32(const void* p) {
    return (uint32_t)__cvta_generic_to_shared(p);
}
__device__ __forceinline__ void bulk_g2s(uint32_t dst, const void* src,
                                         uint32_t bytes, uint32_t mbar) {
    asm volatile(
        "cp.async.bulk.shared::cluster.global.mbarrier::complete_tx::bytes [%0], [%1], %2, [%3];"
        :: "r"(dst), "l"(src), "r"(bytes), "r"(mbar) : "memory");
}
__device__ __forceinline__ void bar_wait(uint32_t mbar, unsigned parity) {
    asm volatile(
        "{\n\t.reg .pred P;\n\t"
        "W_%=:\n\t"
        "mbarrier.try_wait.parity.acquire.cta.shared::cta.b64 P, [%0], %1, 0x989680;\n\t"
        "@P bra D_%=;\n\t"
        "bra W_%=;\n\t"
        "D_%=:\n\t}"
        :: "r"(mbar), "r"(parity) : "memory");
}
#define MBAR_INIT(a, c) \
    asm volatile("mbarrier.init.shared.b64 [%0], %1;" :: "r"(a), "r"(c) : "memory")
#define MBAR_TX(a, b) \
    asm volatile("mbarrier.arrive.expect_tx.shared.b64 _, [%0], %1;" :: "r"(a), "r"(b) : "memory")
#define MBAR_ARRIVE(a) \
    asm volatile("mbarrier.arrive.release.cta.shared::cta.b64 _, [%0];" :: "r"(a) : "memory")

// ---------------------------------------------------------------------------
// Bulk-fed fp16 HMMA GEMM on packed XM tiles, 3-stage ring with per-warp
// empty barriers.  C[m,n] = sum_k A[m,k]*B[n,k].  Block 128 x BROWS x 64.
//  EPI: 0 plain fp32 (+(z%HH)*64 col offset); 1 fp16 XM tiles rows=m;
//       2 fp16 XM tiles rows=n (ETR rows/tile, transposed store)
//  EXS: epilogue stores exp(acc) and atomically accumulates per-row sums
//  SCL: epilogue scales acc by 1/rsum[row]
// ---------------------------------------------------------------------------
template<int AZ, int BZ, int BROWS, int EPI, int ETR, bool EXS, bool SCL>
__global__ __launch_bounds__(256, 2)
void gemm_h(const __half* __restrict__ Apk, const __half* __restrict__ Bpk,
            void* __restrict__ Cg, float* __restrict__ rsum,
            int nkt, int cNK, long czs, long cs1, int ldc)
{
    constexpr int BTH = BROWS * 72;
    constexpr uint32_t ABYT = TH128 * 2, BBYT = BTH * 2;
    constexpr int STAGE = TH128 + BTH;              // halfs per stage
    constexpr int NT = BROWS / 32;

    extern __shared__ __align__(16) __half smem[];
    const uint32_t mb0 = sa32(&smem[0]);            // full[3] @ +0,8,16; empty[3] @ +24,32,40
    __half* tiles = smem + 512;

    const int z = blockIdx.z;
    const long zA = (AZ == 1) ? z / HH : (AZ == 2 ? z % HH : z);
    const long zB = (BZ == 1) ? z / HH : (BZ == 2 ? z % HH : z);
    const __half* Abase = Apk + ((zA * gridDim.y + blockIdx.y) * (long)nkt) * TH128;
    const __half* Bbase = Bpk + ((zB * gridDim.x + blockIdx.x) * (long)nkt) * BTH;

    const int tid = threadIdx.x;
    const int lane = tid & 31;
    const int wid = tid >> 5;
    const int wm = (wid & 1) * 64;
    const int wn = (wid >> 1) * (BROWS / 4);
    const int lm = lane >> 2;
    const int lk = lane & 3;
    const int m0 = blockIdx.y * 128;
    const int n0 = blockIdx.x * BROWS;

    float acc[4][NT][4];
    #pragma unroll
    for (int i = 0; i < 4; i++)
        #pragma unroll
        for (int j = 0; j < NT; j++)
            #pragma unroll
            for (int r = 0; r < 4; r++) acc[i][j][r] = 0.f;

    if (tid == 0) {
        MBAR_INIT(mb0, 1);      MBAR_INIT(mb0 + 8, 1);  MBAR_INIT(mb0 + 16, 1);
        MBAR_INIT(mb0 + 24, 8); MBAR_INIT(mb0 + 32, 8); MBAR_INIT(mb0 + 40, 8);
    }
    __syncthreads();

    auto issue = [&](int st, int kt) {
        const uint32_t m = mb0 + 8 * st;
        MBAR_TX(m, ABYT + BBYT);
        bulk_g2s(sa32(tiles) + st * STAGE * 2, Abase + (long)kt * TH128, ABYT, m);
        bulk_g2s(sa32(tiles) + st * STAGE * 2 + ABYT, Bbase + (long)kt * BTH, BBYT, m);
    };
    if (tid == 0) { issue(0, 0); issue(1, 1); issue(2, 2); }

    auto compute = [&](int st) {
        const __half* __restrict__ Ab = tiles + st * STAGE;
        const __half* __restrict__ Bb = Ab + TH128;
        #pragma unroll
        for (int s = 0; s < 4; s++) {               // 4 x k16 per 64-k stage
            const int kb = s * 16 + 2 * lk;
            unsigned a[4][4], b[NT][2];
            #pragma unroll
            for (int mt = 0; mt < 4; mt++) {
                const int mr = wm + mt * 16 + lm;
                a[mt][0] = *(const unsigned*)&Ab[mr * 72 + kb];
                a[mt][1] = *(const unsigned*)&Ab[(mr + 8) * 72 + kb];
                a[mt][2] = *(const unsigned*)&Ab[mr * 72 + kb + 8];
                a[mt][3] = *(const unsigned*)&Ab[(mr + 8) * 72 + kb + 8];
            }
            #pragma unroll
            for (int nt = 0; nt < NT; nt++) {
                const int nc = wn + nt * 8 + lm;
                b[nt][0] = *(const unsigned*)&Bb[nc * 72 + kb];
                b[nt][1] = *(const unsigned*)&Bb[nc * 72 + kb + 8];
            }
            #pragma unroll
            for (int mt = 0; mt < 4; mt++)
                #pragma unroll
                for (int nt = 0; nt < NT; nt++)
                    mma_f16(acc[mt][nt], a[mt], b[nt]);
        }
    };

    unsigned phF[3] = {0, 0, 0};
    unsigned phE[3] = {0, 0, 0};
    int st = 0;
    for (int t = 0; t < nkt; t++) {
        bar_wait(mb0 + 8 * st, phF[st]);
        phF[st] ^= 1;
        compute(st);
        if (lane == 0) MBAR_ARRIVE(mb0 + 24 + 8 * st);     // warp done with stage
        if (tid == 0 && t + 3 < nkt) {
            bar_wait(mb0 + 24 + 8 * st, phE[st]);          // all 8 warps done
            phE[st] ^= 1;
            issue(st, t + 3);
        }
        st = (st == 2) ? 0 : st + 1;
    }

    // ---- epilogue ----
    #pragma unroll
    for (int mt = 0; mt < 4; mt++) {
        const int rl = wm + mt * 16 + lm;
        const int rg = m0 + rl;
        float s0 = 0.f, s1 = 0.f;                   // EXS row sums
        float i0 = 1.f, i1 = 1.f;
        if (SCL) {
            i0 = 1.0f / rsum[(long)z * LL + rg];
            i1 = 1.0f / rsum[(long)z * LL + rg + 8];
        }
        #pragma unroll
        for (int nt = 0; nt < NT; nt++) {
            const int cl = wn + nt * 8 + 2 * lk;
            const int cg = n0 + cl;
            float v0 = acc[mt][nt][0], v1 = acc[mt][nt][1];
            float v2 = acc[mt][nt][2], v3 = acc[mt][nt][3];
            if (SCL) { v0 *= i0; v1 *= i0; v2 *= i1; v3 *= i1; }
            if (EPI == 0) {
                float* C = (float*)Cg + (long)(z / HH) * cs1 + (long)(z % HH) * 64;
                *(float2*)&C[(long)rg * ldc + cg]       = make_float2(v0, v1);
                *(float2*)&C[(long)(rg + 8) * ldc + cg] = make_float2(v2, v3);
            } else if (EPI == 1) {
                __half* zb = (__half*)Cg + (long)z * czs
                           + ((long)blockIdx.y * cNK + (cg >> 6)) * TH128;
                const int co = cl & 63;
                __half2 h01, h23;
                if (EXS) {
                    h01 = __float22half2_rn(make_float2(__expf(v0), __expf(v1)));
                    h23 = __float22half2_rn(make_float2(__expf(v2), __expf(v3)));
                    const float2 f01 = __half22float2(h01);
                    const float2 f23 = __half22float2(h23);
                    s0 += f01.x + f01.y;
                    s1 += f23.x + f23.y;
                } else {
                    h01 = __float22half2_rn(make_float2(v0, v1));
                    h23 = __float22half2_rn(make_float2(v2, v3));
                }
                *(__half2*)&zb[rl * 72 + co]       = h01;
                *(__half2*)&zb[(rl + 8) * 72 + co] = h23;
            } else {
                __half* zb = (__half*)Cg + (long)z * czs
                           + ((long)(cg / ETR) * cNK + (rg >> 6)) * (ETR * 72);
                const int rr = rg & 63;
                zb[(cg & (ETR - 1)) * 72 + rr]           = __float2half_rn(v0);
                zb[((cg + 1) & (ETR - 1)) * 72 + rr]     = __float2half_rn(v1);
                zb[(cg & (ETR - 1)) * 72 + rr + 8]       = __float2half_rn(v2);
                zb[((cg + 1) & (ETR - 1)) * 72 + rr + 8] = __float2half_rn(v3);
            }
        }
        if (EXS) {                                   // reduce across the 4 lk lanes
            s0 += __shfl_xor_sync(~0u, s0, 1); s0 += __shfl_xor_sync(~0u, s0, 2);
            s1 += __shfl_xor_sync(~0u, s1, 1); s1 += __shfl_xor_sync(~0u, s1, 2);
            if (lk == 0) {
                atomicAdd(&rsum[(long)z * LL + rg], s0);
                atomicAdd(&rsum[(long)z * LL + rg + 8], s1);
            }
        }
    }
}

// ---------------------------------------------------------------------------
// Pack kernels: fp32 -> fp16 XM stride-72 tiles.
// ---------------------------------------------------------------------------
__global__ void pack_x(const float* __restrict__ x, __half* __restrict__ xp) {
    __half* blob = xp + (((long)blockIdx.z * 8 + blockIdx.y) * 12 + blockIdx.x) * TH128;
    const float* src = x + ((long)(blockIdx.z * LL + blockIdx.y * 128)) * DD + blockIdx.x * 64;
    #pragma unroll
    for (int i = 0; i < 8; i++) {
        const int s = threadIdx.x + i * 256;
        const int row = s >> 4, c4 = (s & 15) << 2;
        const float4 v = *(const float4*)&src[(long)row * DD + c4];
        *(__half2*)&blob[row * 72 + c4]     = __float22half2_rn(make_float2(v.x, v.y));
        *(__half2*)&blob[row * 72 + c4 + 2] = __float22half2_rn(make_float2(v.z, v.w));
    }
}
__global__ void pack_qk(const float* __restrict__ in, __half* __restrict__ op) {
    __half* blob = op + (((long)blockIdx.z * 6 + blockIdx.y) * 12 + blockIdx.x) * TH128;
    const float* src = in + ((long)blockIdx.z * DD + blockIdx.x * 64) * DD + blockIdx.y * 128;
    #pragma unroll
    for (int i = 0; i < 8; i++) {
        const int s = threadIdx.x + i * 256;
        const int c = s >> 5, x0 = (s & 31) << 2;
        const float4 v = *(const float4*)&src[(long)c * DD + x0];
        blob[(x0 + 0) * 72 + c] = __float2half_rn(v.x);
        blob[(x0 + 1) * 72 + c] = __float2half_rn(v.y);
        blob[(x0 + 2) * 72 + c] = __float2half_rn(v.z);
        blob[(x0 + 3) * 72 + c] = __float2half_rn(v.w);
    }
}
__global__ void pack_v(const float* __restrict__ v, __half* __restrict__ vp) {
    __half* blob = vp + ((long)blockIdx.y * 12 + blockIdx.x) * TH64;
    const float* src = v + (long)blockIdx.y * DHH * DD + blockIdx.x * 64;
    #pragma unroll
    for (int i = 0; i < 4; i++) {
        const int s = threadIdx.x + i * 256;
        const int row = s >> 4, c4 = (s & 15) << 2;
        const float4 w = *(const float4*)&src[(long)row * DD + c4];
        *(__half2*)&blob[row * 72 + c4]     = __float22half2_rn(make_float2(w.x, w.y));
        *(__half2*)&blob[row * 72 + c4 + 2] = __float22half2_rn(make_float2(w.z, w.w));
    }
}

// ---------------------------------------------------------------------------
extern "C" void kernel_launch(void* const* d_in, const int* in_sizes, int n_in,
                              void* d_out, int out_size)
{
    const float* x = (const float*)d_in[0];
    const float* k = (const float*)d_in[1];
    const float* q = (const float*)d_in[2];
    const float* v = (const float*)d_in[3];
    float* out = (float*)d_out;

    __half *xp, *qp, *kp, *vp, *Mp, *Ap, *Sp, *Vtp;
    float* rs;
    cudaGetSymbolAddress((void**)&xp, g_xp);
    cudaGetSymbolAddress((void**)&qp, g_qp);
    cudaGetSymbolAddress((void**)&kp, g_kp);
    cudaGetSymbolAddress((void**)&vp, g_vp);
    cudaGetSymbolAddress((void**)&Mp, g_Mp);
    cudaGetSymbolAddress((void**)&Ap, g_Ap);
    cudaGetSymbolAddress((void**)&Sp, g_Sp);
    cudaGetSymbolAddress((void**)&Vtp, g_Vtp);
    cudaGetSymbolAddress((void**)&rs, g_rsum);

    const int SM128 = 1024 + 3 * (18432 + 18432);   // 111616
    const int SM64  = 1024 + 3 * (18432 + 9216);    // 83968

    auto* G1 = gemm_h<0, 0, 128, 2, 128, false, false>;
    auto* G2 = gemm_h<1, 2, 128, 1, 0, false, false>;
    auto* G3 = gemm_h<0, 1, 128, 1, 0, true, false>;
    auto* G5 = gemm_h<1, 2, 64, 2, 64, false, false>;
    auto* G6 = gemm_h<0, 0, 64, 0, 0, false, true>;
    cudaFuncSetAttribute(G1, cudaFuncAttributeMaxDynamicSharedMemorySize, SM128);
    cudaFuncSetAttribute(G2, cudaFuncAttributeMaxDynamicSharedMemorySize, SM128);
    cudaFuncSetAttribute(G3, cudaFuncAttributeMaxDynamicSharedMemorySize, SM128);
    cudaFuncSetAttribute(G5, cudaFuncAttributeMaxDynamicSharedMemorySize, SM64);
    cudaFuncSetAttribute(G6, cudaFuncAttributeMaxDynamicSharedMemorySize, SM64);

    // 0) pack inputs (fp16) + zero row-sum accumulator
    cudaMemsetAsync(rs, 0, (size_t)BB * HH * LL * sizeof(float), 0);
    pack_x <<<dim3(12, 8, BB), 256>>>(x, xp);
    pack_qk<<<dim3(12, 6, HH), 256>>>(q, qp);
    pack_qk<<<dim3(12, 6, HH), 256>>>(k, kp);
    pack_v <<<dim3(12, HH), 256>>>(v, vp);

    // 1) M^T[e,d] = sum_c q[c,d] k[c,e]
    G1<<<dim3(6, 6, HH), 256, SM128>>>(qp, kp, Mp, rs, 12, 12, 6L * 12 * TH128, 0, 0);

    // 2) A[l,e] = sum_d x[l,d] M^T[e,d]
    G2<<<dim3(6, 8, BB * HH), 256, SM128>>>(xp, Mp, Ap, rs, 12, 12, 8L * 12 * TH128, 0, 0);

    // 3) P[l,m] = exp(sum_e A[l,e] x[m,e]); rsum[l] += row sums (atomic)
    G3<<<dim3(8, 8, BB * HH), 256, SM128>>>(Ap, xp, Sp, rs, 12, 16, 8L * 16 * TH128, 0, 0);

    // 5) Vt[j,l] = sum_d x[l,d] v[j,d]
    G5<<<dim3(1, 8, BB * HH), 256, SM64>>>(xp, vp, Vtp, rs, 12, 16, 16L * TH64, 0, 0);

    // 6) out[l, h*64+j] = (sum_m P[l,m] Vt[j,m]) / rsum[l]
    G6<<<dim3(1, 8, BB * HH), 256, SM64>>>(Sp, Vtp, out, rs, 16, 0, 0, (long)LL * DD, DD);
}

// round 11
// speedup vs baseline: 2.5351x; 1.0347x over previous
#include <cuda_runtime.h>
#include <cuda_fp16.h>
#include <cstdint>

#define BB 4
#define LL 1024
#define DD 768
#define HH 12
#define DHH 64

// Packed fp16 scratch: XM tiles, k-contiguous, k-chunks of 64.
//   128-row tile = 128 x 72 halfs (64 data + 8 pad) = 18432B
//   64-row tile  =  64 x 72 halfs = 9216B
#define TH128 9216
#define TH64  4608
__device__ __align__(1024) __half g_xp [(size_t)BB * 8 * 12 * TH128];
__device__ __align__(1024) __half g_qp [(size_t)HH * 6 * 12 * TH128];
__device__ __align__(1024) __half g_kp [(size_t)HH * 6 * 12 * TH128];
__device__ __align__(1024) __half g_vp [(size_t)HH * 12 * TH64];
__device__ __align__(1024) __half g_Mp [(size_t)HH * 6 * 12 * TH128];
__device__ __align__(1024) __half g_Ap [(size_t)BB * HH * 8 * 12 * TH128];
__device__ __align__(1024) __half g_Sp [(size_t)BB * HH * 8 * 16 * TH128]; // P = exp(S)
__device__ __align__(1024) __half g_Vtp[(size_t)BB * HH * 16 * TH64];
__device__ float g_rsum[(size_t)BB * HH * LL];       // per-row sums of exp(S)

__device__ __forceinline__ void mma_f16(float* c, const unsigned* a, const unsigned* b) {
    asm volatile(
        "mma.sync.aligned.m16n8k16.row.col.f32.f16.f16.f32 "
        "{%0,%1,%2,%3}, {%4,%5,%6,%7}, {%8,%9}, {%0,%1,%2,%3};"
        : "+f"(c[0]), "+f"(c[1]), "+f"(c[2]), "+f"(c[3])
        : "r"(a[0]), "r"(a[1]), "r"(a[2]), "r"(a[3]), "r"(b[0]), "r"(b[1]));
}

__device__ __forceinline__ uint32_t sa32(const void* p) {
    return (uint32_t)__cvta_generic_to_shared(p);
}
__device__ __forceinline__ void bulk_g2s(uint32_t dst, const void* src,
                                         uint32_t bytes, uint32_t mbar) {
    asm volatile(
        "cp.async.bulk.shared::cluster.global.mbarrier::complete_tx::bytes [%0], [%1], %2, [%3];"
        :: "r"(dst), "l"(src), "r"(bytes), "r"(mbar) : "memory");
}
__device__ __forceinline__ void bar_wait(uint32_t mbar, unsigned parity) {
    asm volatile(
        "{\n\t.reg .pred P;\n\t"
        "W_%=:\n\t"
        "mbarrier.try_wait.parity.acquire.cta.shared::cta.b64 P, [%0], %1, 0x989680;\n\t"
        "@P bra D_%=;\n\t"
        "bra W_%=;\n\t"
        "D_%=:\n\t}"
        :: "r"(mbar), "r"(parity) : "memory");
}
#define MBAR_INIT(a, c) \
    asm volatile("mbarrier.init.shared.b64 [%0], %1;" :: "r"(a), "r"(c) : "memory")
#define MBAR_TX(a, b) \
    asm volatile("mbarrier.arrive.expect_tx.shared.b64 _, [%0], %1;" :: "r"(a), "r"(b) : "memory")
#define MBAR_ARRIVE(a) \
    asm volatile("mbarrier.arrive.release.cta.shared::cta.b64 _, [%0];" :: "r"(a) : "memory")

// ---------------------------------------------------------------------------
// GEMM body as a device function (so independent GEMMs can share one launch).
//  C[m,n] = sum_k A[m,k]*B[n,k].  Block 128 x BROWS x 64, 3-stage bulk ring,
//  per-warp empty barriers.
//  EPI: 0 plain fp32 (+(z%HH)*64 col offset); 1 fp16 XM tiles rows=m;
//       2 fp16 XM tiles rows=n (ETR rows/tile, transposed store)
//  EXS: store exp(acc), atomically accumulate per-row sums
//  SCL: scale acc by 1/rsum[row]
// ---------------------------------------------------------------------------
template<int AZ, int BZ, int BROWS, int EPI, int ETR, bool EXS, bool SCL>
__device__ __forceinline__
void gemm_dev(const __half* __restrict__ Apk, const __half* __restrict__ Bpk,
              void* __restrict__ Cg, float* __restrict__ rsum,
              int nkt, int cNK, long czs, long cs1, int ldc,
              int bx, int by, int bz, int gdx, int gdy, __half* smem)
{
    constexpr int BTH = BROWS * 72;
    constexpr uint32_t ABYT = TH128 * 2, BBYT = BTH * 2;
    constexpr int STAGE = TH128 + BTH;              // halfs per stage
    constexpr int NT = BROWS / 32;

    const uint32_t mb0 = sa32(&smem[0]);            // full[3] @ +0,8,16; empty[3] @ +24,32,40
    __half* tiles = smem + 512;

    const int z = bz;
    const long zA = (AZ == 1) ? z / HH : (AZ == 2 ? z % HH : z);
    const long zB = (BZ == 1) ? z / HH : (BZ == 2 ? z % HH : z);
    const __half* Abase = Apk + ((zA * gdy + by) * (long)nkt) * TH128;
    const __half* Bbase = Bpk + ((zB * gdx + bx) * (long)nkt) * BTH;

    const int tid = threadIdx.x;
    const int lane = tid & 31;
    const int wid = tid >> 5;
    const int wm = (wid & 1) * 64;
    const int wn = (wid >> 1) * (BROWS / 4);
    const int lm = lane >> 2;
    const int lk = lane & 3;
    const int m0 = by * 128;
    const int n0 = bx * BROWS;

    float acc[4][NT][4];
    #pragma unroll
    for (int i = 0; i < 4; i++)
        #pragma unroll
        for (int j = 0; j < NT; j++)
            #pragma unroll
            for (int r = 0; r < 4; r++) acc[i][j][r] = 0.f;

    if (tid == 0) {
        MBAR_INIT(mb0, 1);      MBAR_INIT(mb0 + 8, 1);  MBAR_INIT(mb0 + 16, 1);
        MBAR_INIT(mb0 + 24, 8); MBAR_INIT(mb0 + 32, 8); MBAR_INIT(mb0 + 40, 8);
    }
    __syncthreads();

    auto issue = [&](int st, int kt) {
        const uint32_t m = mb0 + 8 * st;
        MBAR_TX(m, ABYT + BBYT);
        bulk_g2s(sa32(tiles) + st * STAGE * 2, Abase + (long)kt * TH128, ABYT, m);
        bulk_g2s(sa32(tiles) + st * STAGE * 2 + ABYT, Bbase + (long)kt * BTH, BBYT, m);
    };
    if (tid == 0) { issue(0, 0); issue(1, 1); issue(2, 2); }

    auto compute = [&](int st) {
        const __half* __restrict__ Ab = tiles + st * STAGE;
        const __half* __restrict__ Bb = Ab + TH128;
        #pragma unroll
        for (int s = 0; s < 4; s++) {               // 4 x k16 per 64-k stage
            const int kb = s * 16 + 2 * lk;
            unsigned a[4][4], b[NT][2];
            #pragma unroll
            for (int mt = 0; mt < 4; mt++) {
                const int mr = wm + mt * 16 + lm;
                a[mt][0] = *(const unsigned*)&Ab[mr * 72 + kb];
                a[mt][1] = *(const unsigned*)&Ab[(mr + 8) * 72 + kb];
                a[mt][2] = *(const unsigned*)&Ab[mr * 72 + kb + 8];
                a[mt][3] = *(const unsigned*)&Ab[(mr + 8) * 72 + kb + 8];
            }
            #pragma unroll
            for (int nt = 0; nt < NT; nt++) {
                const int nc = wn + nt * 8 + lm;
                b[nt][0] = *(const unsigned*)&Bb[nc * 72 + kb];
                b[nt][1] = *(const unsigned*)&Bb[nc * 72 + kb + 8];
            }
            #pragma unroll
            for (int mt = 0; mt < 4; mt++)
                #pragma unroll
                for (int nt = 0; nt < NT; nt++)
                    mma_f16(acc[mt][nt], a[mt], b[nt]);
        }
    };

    unsigned phF[3] = {0, 0, 0};
    unsigned phE[3] = {0, 0, 0};
    int st = 0;
    for (int t = 0; t < nkt; t++) {
        bar_wait(mb0 + 8 * st, phF[st]);
        phF[st] ^= 1;
        compute(st);
        if (lane == 0) MBAR_ARRIVE(mb0 + 24 + 8 * st);     // warp done with stage
        if (tid == 0 && t + 3 < nkt) {
            bar_wait(mb0 + 24 + 8 * st, phE[st]);          // all 8 warps done
            phE[st] ^= 1;
            issue(st, t + 3);
        }
        st = (st == 2) ? 0 : st + 1;
    }

    // ---- epilogue ----
    #pragma unroll
    for (int mt = 0; mt < 4; mt++) {
        const int rl = wm + mt * 16 + lm;
        const int rg = m0 + rl;
        float s0 = 0.f, s1 = 0.f;
        float i0 = 1.f, i1 = 1.f;
        if (SCL) {
            i0 = 1.0f / rsum[(long)z * LL + rg];
            i1 = 1.0f / rsum[(long)z * LL + rg + 8];
        }
        #pragma unroll
        for (int nt = 0; nt < NT; nt++) {
            const int cl = wn + nt * 8 + 2 * lk;
            const int cg = n0 + cl;
            float v0 = acc[mt][nt][0], v1 = acc[mt][nt][1];
            float v2 = acc[mt][nt][2], v3 = acc[mt][nt][3];
            if (SCL) { v0 *= i0; v1 *= i0; v2 *= i1; v3 *= i1; }
            if (EPI == 0) {
                float* C = (float*)Cg + (long)(z / HH) * cs1 + (long)(z % HH) * 64;
                *(float2*)&C[(long)rg * ldc + cg]       = make_float2(v0, v1);
                *(float2*)&C[(long)(rg + 8) * ldc + cg] = make_float2(v2, v3);
            } else if (EPI == 1) {
                __half* zb = (__half*)Cg + (long)z * czs
                           + ((long)by * cNK + (cg >> 6)) * TH128;
                const int co = cl & 63;
                __half2 h01, h23;
                if (EXS) {
                    h01 = __float22half2_rn(make_float2(__expf(v0), __expf(v1)));
                    h23 = __float22half2_rn(make_float2(__expf(v2), __expf(v3)));
                    const float2 f01 = __half22float2(h01);
                    const float2 f23 = __half22float2(h23);
                    s0 += f01.x + f01.y;
                    s1 += f23.x + f23.y;
                } else {
                    h01 = __float22half2_rn(make_float2(v0, v1));
                    h23 = __float22half2_rn(make_float2(v2, v3));
                }
                *(__half2*)&zb[rl * 72 + co]       = h01;
                *(__half2*)&zb[(rl + 8) * 72 + co] = h23;
            } else {
                __half* zb = (__half*)Cg + (long)z * czs
                           + ((long)(cg / ETR) * cNK + (rg >> 6)) * (ETR * 72);
                const int rr = rg & 63;
                zb[(cg & (ETR - 1)) * 72 + rr]           = __float2half_rn(v0);
                zb[((cg + 1) & (ETR - 1)) * 72 + rr]     = __float2half_rn(v1);
                zb[(cg & (ETR - 1)) * 72 + rr + 8]       = __float2half_rn(v2);
                zb[((cg + 1) & (ETR - 1)) * 72 + rr + 8] = __float2half_rn(v3);
            }
        }
        if (EXS) {
            s0 += __shfl_xor_sync(~0u, s0, 1); s0 += __shfl_xor_sync(~0u, s0, 2);
            s1 += __shfl_xor_sync(~0u, s1, 1); s1 += __shfl_xor_sync(~0u, s1, 2);
            if (lk == 0) {
                atomicAdd(&rsum[(long)z * LL + rg], s0);
                atomicAdd(&rsum[(long)z * LL + rg + 8], s1);
            }
        }
    }
}

// ---- standalone GEMM kernels --------------------------------------------
template<int AZ, int BZ, int BROWS, int EPI, int ETR, bool EXS, bool SCL>
__global__ __launch_bounds__(256, 2)
void gemm_k(const __half* __restrict__ Apk, const __half* __restrict__ Bpk,
            void* __restrict__ Cg, float* __restrict__ rsum,
            int nkt, int cNK, long czs, long cs1, int ldc)
{
    extern __shared__ __align__(16) __half smem[];
    gemm_dev<AZ, BZ, BROWS, EPI, ETR, EXS, SCL>(
        Apk, Bpk, Cg, rsum, nkt, cNK, czs, cs1, ldc,
        blockIdx.x, blockIdx.y, blockIdx.z, gridDim.x, gridDim.y, smem);
}

// ---- fused G1 (M^T = q^T k) + G5 (Vt = x v^T) in one launch ---------------
__global__ __launch_bounds__(256, 2)
void gemm_g1g5(const __half* __restrict__ qp, const __half* __restrict__ kp,
               __half* __restrict__ Mp,
               const __half* __restrict__ xp, const __half* __restrict__ vp,
               __half* __restrict__ Vtp)
{
    extern __shared__ __align__(16) __half smem[];
    const int bid = blockIdx.x;
    if (bid < 432) {                                // G1: grid (6,6,12)
        gemm_dev<0, 0, 128, 2, 128, false, false>(
            qp, kp, Mp, nullptr, 12, 12, 6L * 12 * TH128, 0, 0,
            bid % 6, (bid / 6) % 6, bid / 36, 6, 6, smem);
    } else {                                        // G5: grid (1,8,48)
        const int t = bid - 432;
        gemm_dev<1, 2, 64, 2, 64, false, false>(
            xp, vp, Vtp, nullptr, 12, 16, 16L * TH64, 0, 0,
            0, t % 8, t / 8, 1, 8, smem);
    }
}

// ---------------------------------------------------------------------------
// Fused pack kernel: all input packing + rsum zeroing in one launch.
// Block ranges: [0,384) pack_x | [384,1248) pack q | [1248,2112) pack k
//               [2112,2256) pack v | [2256,2304) zero rsum
// ---------------------------------------------------------------------------
__device__ __forceinline__
void pack_x_dev(const float* __restrict__ x, __half* __restrict__ xp,
                int kx, int ly, int bz) {
    __half* blob = xp + (((long)bz * 8 + ly) * 12 + kx) * TH128;
    const float* src = x + ((long)(bz * LL + ly * 128)) * DD + kx * 64;
    #pragma unroll
    for (int i = 0; i < 8; i++) {
        const int s = threadIdx.x + i * 256;
        const int row = s >> 4, c4 = (s & 15) << 2;
        const float4 v = *(const float4*)&src[(long)row * DD + c4];
        *(__half2*)&blob[row * 72 + c4]     = __float22half2_rn(make_float2(v.x, v.y));
        *(__half2*)&blob[row * 72 + c4 + 2] = __float22half2_rn(make_float2(v.z, v.w));
    }
}
__device__ __forceinline__
void pack_qk_dev(const float* __restrict__ in, __half* __restrict__ op,
                 int kx, int xy, int hz) {
    __half* blob = op + (((long)hz * 6 + xy) * 12 + kx) * TH128;
    const float* src = in + ((long)hz * DD + kx * 64) * DD + xy * 128;
    #pragma unroll
    for (int i = 0; i < 8; i++) {
        const int s = threadIdx.x + i * 256;
        const int c = s >> 5, x0 = (s & 31) << 2;
        const float4 v = *(const float4*)&src[(long)c * DD + x0];
        blob[(x0 + 0) * 72 + c] = __float2half_rn(v.x);
        blob[(x0 + 1) * 72 + c] = __float2half_rn(v.y);
        blob[(x0 + 2) * 72 + c] = __float2half_rn(v.z);
        blob[(x0 + 3) * 72 + c] = __float2half_rn(v.w);
    }
}
__device__ __forceinline__
void pack_v_dev(const float* __restrict__ v, __half* __restrict__ vp,
                int kx, int hy) {
    __half* blob = vp + ((long)hy * 12 + kx) * TH64;
    const float* src = v + (long)hy * DHH * DD + kx * 64;
    #pragma unroll
    for (int i = 0; i < 4; i++) {
        const int s = threadIdx.x + i * 256;
        const int row = s >> 4, c4 = (s & 15) << 2;
        const float4 w = *(const float4*)&src[(long)row * DD + c4];
        *(__half2*)&blob[row * 72 + c4]     = __float22half2_rn(make_float2(w.x, w.y));
        *(__half2*)&blob[row * 72 + c4 + 2] = __float22half2_rn(make_float2(w.z, w.w));
    }
}

__global__ void pack_all(const float* __restrict__ x, const float* __restrict__ q,
                         const float* __restrict__ k, const float* __restrict__ v,
                         __half* __restrict__ xp, __half* __restrict__ qp,
                         __half* __restrict__ kp, __half* __restrict__ vp,
                         float* __restrict__ rsum)
{
    const int bid = blockIdx.x;
    if (bid < 384) {
        pack_x_dev(x, xp, bid % 12, (bid / 12) % 8, bid / 96);
    } else if (bid < 1248) {
        const int t = bid - 384;
        pack_qk_dev(q, qp, t % 12, (t / 12) % 6, t / 72);
    } else if (bid < 2112) {
        const int t = bid - 1248;
        pack_qk_dev(k, kp, t % 12, (t / 12) % 6, t / 72);
    } else if (bid < 2256) {
        const int t = bid - 2112;
        pack_v_dev(v, vp, t % 12, t / 12);
    } else {
        const int t = bid - 2256;                   // zero rsum: 48 x 1024 floats
        float4* dst = (float4*)&rsum[(long)t * LL];
        dst[threadIdx.x] = make_float4(0.f, 0.f, 0.f, 0.f);
    }
}

// ---------------------------------------------------------------------------
extern "C" void kernel_launch(void* const* d_in, const int* in_sizes, int n_in,
                              void* d_out, int out_size)
{
    const float* x = (const float*)d_in[0];
    const float* k = (const float*)d_in[1];
    const float* q = (const float*)d_in[2];
    const float* v = (const float*)d_in[3];
    float* out = (float*)d_out;

    __half *xp, *qp, *kp, *vp, *Mp, *Ap, *Sp, *Vtp;
    float* rs;
    cudaGetSymbolAddress((void**)&xp, g_xp);
    cudaGetSymbolAddress((void**)&qp, g_qp);
    cudaGetSymbolAddress((void**)&kp, g_kp);
    cudaGetSymbolAddress((void**)&vp, g_vp);
    cudaGetSymbolAddress((void**)&Mp, g_Mp);
    cudaGetSymbolAddress((void**)&Ap, g_Ap);
    cudaGetSymbolAddress((void**)&Sp, g_Sp);
    cudaGetSymbolAddress((void**)&Vtp, g_Vtp);
    cudaGetSymbolAddress((void**)&rs, g_rsum);

    const int SM128 = 1024 + 3 * (18432 + 18432);   // 111616
    const int SM64  = 1024 + 3 * (18432 + 9216);    // 83968

    auto* G2 = gemm_k<1, 2, 128, 1, 0, false, false>;
    auto* G3 = gemm_k<0, 1, 128, 1, 0, true, false>;
    auto* G6 = gemm_k<0, 0, 64, 0, 0, false, true>;
    cudaFuncSetAttribute(gemm_g1g5, cudaFuncAttributeMaxDynamicSharedMemorySize, SM128);
    cudaFuncSetAttribute(G2, cudaFuncAttributeMaxDynamicSharedMemorySize, SM128);
    cudaFuncSetAttribute(G3, cudaFuncAttributeMaxDynamicSharedMemorySize, SM128);
    cudaFuncSetAttribute(G6, cudaFuncAttributeMaxDynamicSharedMemorySize, SM64);

    // 0) pack inputs + zero rsum, one launch
    pack_all<<<dim3(2304), 256>>>(x, q, k, v, xp, qp, kp, vp, rs);

    // 1+5) M^T = q^T k  and  Vt = x v^T, one launch (independent GEMMs)
    gemm_g1g5<<<dim3(816), 256, SM128>>>(qp, kp, Mp, xp, vp, Vtp);

    // 2) A[l,e] = sum_d x[l,d] M^T[e,d]
    G2<<<dim3(6, 8, BB * HH), 256, SM128>>>(xp, Mp, Ap, rs, 12, 12, 8L * 12 * TH128, 0, 0);

    // 3) P[l,m] = exp(sum_e A[l,e] x[m,e]); rsum[l] += row sums (atomic)
    G3<<<dim3(8, 8, BB * HH), 256, SM128>>>(Ap, xp, Sp, rs, 12, 16, 8L * 16 * TH128, 0, 0);

    // 6) out[l, h*64+j] = (sum_m P[l,m] Vt[j,m]) / rsum[l]
    G6<<<dim3(1, 8, BB * HH), 256, SM64>>>(Sp, Vtp, out, rs, 16, 0, 0, (long)LL * DD, DD);
}